// round 3
// baseline (speedup 1.0000x reference)
#include <cuda_runtime.h>
#include <cuda_bf16.h>
#include <math.h>

// Problem constants
#define B_ 2
#define S_ 2048
#define HID_ 2048
#define NH_ 8
#define HD_ 256
#define M_ 4096           // B*S
#define QKDIM_ (NH_*HD_)  // 2048

// Scratch (device globals: allocation-free per harness rules)
__device__ float g_q[M_ * QKDIM_];   // 32 MB  [b,s, h*HD+d]
__device__ float g_k[M_ * HD_];      // 4 MB   [b,s, d]
__device__ float g_v[M_ * HD_];      // 4 MB
__device__ float g_att[M_ * QKDIM_]; // 32 MB

// ---------------------------------------------------------------------------
// SGEMM: C[M,N] = A[M,K] @ W[K,N], all row-major fp32.
// 128x128 tile, BK=16, 256 threads, 8x8 per thread.
// ---------------------------------------------------------------------------
__global__ __launch_bounds__(256) void sgemm_kernel(
    const float* __restrict__ A, const float* __restrict__ Bw,
    float* __restrict__ C, int M, int N, int K)
{
    constexpr int BM = 128, BN = 128, BK = 16;
    __shared__ float As[BK][BM + 4];
    __shared__ float Bs[BK][BN];

    const int tid = threadIdx.x;
    const int tx  = tid & 15;
    const int ty  = tid >> 4;
    const int row0 = blockIdx.y * BM;
    const int col0 = blockIdx.x * BN;

    float acc[8][8];
    #pragma unroll
    for (int i = 0; i < 8; i++)
        #pragma unroll
        for (int j = 0; j < 8; j++) acc[i][j] = 0.f;

    const int ar = tid >> 2;          // 0..63
    const int ac = (tid & 3) << 2;    // 0,4,8,12
    const int br = tid >> 5;          // 0..7
    const int bc = (tid & 31) << 2;   // 0..124

    for (int k0 = 0; k0 < K; k0 += BK) {
        #pragma unroll
        for (int hh = 0; hh < 2; ++hh) {
            const int r = ar + hh * 64;
            float4 a4 = *(const float4*)(A + (size_t)(row0 + r) * K + k0 + ac);
            As[ac + 0][r] = a4.x; As[ac + 1][r] = a4.y;
            As[ac + 2][r] = a4.z; As[ac + 3][r] = a4.w;
        }
        #pragma unroll
        for (int hh = 0; hh < 2; ++hh) {
            const int r = br + hh * 8;
            *(float4*)(&Bs[r][bc]) =
                *(const float4*)(Bw + (size_t)(k0 + r) * N + col0 + bc);
        }
        __syncthreads();
        #pragma unroll
        for (int kk = 0; kk < BK; ++kk) {
            float a_[8], b_[8];
            #pragma unroll
            for (int i = 0; i < 8; i++) a_[i] = As[kk][ty * 8 + i];
            #pragma unroll
            for (int j = 0; j < 8; j++) b_[j] = Bs[kk][tx * 8 + j];
            #pragma unroll
            for (int i = 0; i < 8; i++)
                #pragma unroll
                for (int j = 0; j < 8; j++)
                    acc[i][j] = fmaf(a_[i], b_[j], acc[i][j]);
        }
        __syncthreads();
    }

    #pragma unroll
    for (int i = 0; i < 8; i++) {
        float* cp = C + (size_t)(row0 + ty * 8 + i) * N + col0 + tx * 8;
        float4 v0; v0.x = acc[i][0]; v0.y = acc[i][1]; v0.z = acc[i][2]; v0.w = acc[i][3];
        float4 v1; v1.x = acc[i][4]; v1.y = acc[i][5]; v1.z = acc[i][6]; v1.w = acc[i][7];
        *(float4*)cp       = v0;
        *(float4*)(cp + 4) = v1;
    }
}

// ---------------------------------------------------------------------------
// RoPE (in-place on q and k). One thread per (first-half, second-half) pair.
// ---------------------------------------------------------------------------
__global__ void rope_kernel(float* __restrict__ q, float* __restrict__ k,
                            const int* __restrict__ pos)
{
    const int QP = B_ * S_ * NH_ * (HD_ / 2);   // 4194304
    const int KP = B_ * S_ * (HD_ / 2);         //  524288
    int idx = blockIdx.x * blockDim.x + threadIdx.x;
    if (idx >= QP + KP) return;

    const float L2B = 13.28771237954945f;  // log2(10000)

    if (idx < QP) {
        const int i  = idx & 127;
        const int h  = (idx >> 7) & 7;
        const int bs = idx >> 10;
        const float inv = exp2f(-(float)(2 * i) * (L2B / 256.f));
        const float ang = (float)pos[bs] * inv;
        float sn, cs; sincosf(ang, &sn, &cs);
        float* base = q + (size_t)bs * QKDIM_ + h * HD_;
        const float x1 = base[i], x2 = base[i + 128];
        base[i]       = x1 * cs - x2 * sn;
        base[i + 128] = x2 * cs + x1 * sn;
    } else {
        const int j  = idx - QP;
        const int i  = j & 127;
        const int bs = j >> 7;
        const float inv = exp2f(-(float)(2 * i) * (L2B / 256.f));
        const float ang = (float)pos[bs] * inv;
        float sn, cs; sincosf(ang, &sn, &cs);
        float* base = k + (size_t)bs * HD_;
        const float x1 = base[i], x2 = base[i + 128];
        base[i]       = x1 * cs - x2 * sn;
        base[i + 128] = x2 * cs + x1 * sn;
    }
}

// ---------------------------------------------------------------------------
// Flash attention (fp32, causal, MQA). One CTA = (b, h, 64-row q tile).
// 256 threads. Q tile resident in SMEM; K then V streamed through one
// padded [64][260] buffer. Online softmax by 64 row-threads.
// Thread (ty,tx): ty=tid/16 owns rows ty*4+r; tx owns cols c*16+tx.
// ---------------------------------------------------------------------------
#define ATTN_SMEM_FLOATS (64*256 + 64*260 + 64*64 + 3*64)
#define ATTN_SMEM_BYTES  (ATTN_SMEM_FLOATS * 4)

__global__ __launch_bounds__(256, 1) void attn_kernel(
    const float* __restrict__ q, const float* __restrict__ kmat,
    const float* __restrict__ v, float* __restrict__ o)
{
    extern __shared__ float sm[];
    float* Qs = sm;                 // [64][256]
    float* Ks = sm + 64 * 256;      // [64][260]  (K, then reused for V)
    float* Ps = Ks + 64 * 260;      // [64][64]
    float* Ms = Ps + 64 * 64;       // [64] running max
    float* Ls = Ms + 64;            // [64] running sum
    float* Cr = Ls + 64;            // [64] correction factor

    const int qt = (int)gridDim.x - 1 - (int)blockIdx.x;  // heavy tiles first
    const int h  = blockIdx.y;
    const int b  = blockIdx.z;
    const int tid = threadIdx.x;
    const int tx  = tid & 15;
    const int ty  = tid >> 4;
    const int row0 = ty * 4;
    const int q0 = qt * 64;
    const float scale = 0.0625f;    // 1/sqrt(256)

    // Load Q tile [64][256]
    for (int t = tid; t < 4096; t += 256) {
        const int r = t >> 6, c4 = t & 63;
        float4 val = *(const float4*)(q + (size_t)(b * S_ + q0 + r) * QKDIM_
                                        + h * HD_ + c4 * 4);
        *(float4*)(Qs + r * 256 + c4 * 4) = val;
    }
    if (tid < 64) { Ms[tid] = -INFINITY; Ls[tid] = 0.f; Cr[tid] = 0.f; }

    float acc[4][16];
    #pragma unroll
    for (int r = 0; r < 4; r++)
        #pragma unroll
        for (int c = 0; c < 16; c++) acc[r][c] = 0.f;

    for (int kt = 0; kt <= qt; ++kt) {
        const int k0 = kt * 64;
        __syncthreads();  // prev PV done with Vs (and 1st iter: Q/Ms visible)

        // Load K tile -> Ks
        for (int t = tid; t < 4096; t += 256) {
            const int r = t >> 6, c4 = t & 63;
            float4 val = *(const float4*)(kmat + (size_t)(b * S_ + k0 + r) * HD_ + c4 * 4);
            *(float4*)(Ks + r * 260 + c4 * 4) = val;
        }
        __syncthreads();

        // S = Q @ K^T  (4x4 per thread), vectorized over d by 4
        float sacc[4][4];
        #pragma unroll
        for (int r = 0; r < 4; r++)
            #pragma unroll
            for (int c = 0; c < 4; c++) sacc[r][c] = 0.f;

        for (int k4 = 0; k4 < 256; k4 += 4) {
            float4 qv[4], kv[4];
            #pragma unroll
            for (int r = 0; r < 4; r++)
                qv[r] = *(const float4*)(Qs + (row0 + r) * 256 + k4);
            #pragma unroll
            for (int c = 0; c < 4; c++)
                kv[c] = *(const float4*)(Ks + (c * 16 + tx) * 260 + k4);
            #pragma unroll
            for (int r = 0; r < 4; r++)
                #pragma unroll
                for (int c = 0; c < 4; c++) {
                    sacc[r][c] = fmaf(qv[r].x, kv[c].x, sacc[r][c]);
                    sacc[r][c] = fmaf(qv[r].y, kv[c].y, sacc[r][c]);
                    sacc[r][c] = fmaf(qv[r].z, kv[c].z, sacc[r][c]);
                    sacc[r][c] = fmaf(qv[r].w, kv[c].w, sacc[r][c]);
                }
        }

        // Scale + causal mask, write to Ps
        #pragma unroll
        for (int r = 0; r < 4; r++)
            #pragma unroll
            for (int c = 0; c < 4; c++) {
                const int col = c * 16 + tx;
                float s = sacc[r][c] * scale;
                if (k0 + col > q0 + row0 + r) s = -1e30f;
                Ps[(row0 + r) * 64 + col] = s;
            }
        __syncthreads();

        // Load V tile -> Ks (overwrites K; all its readers are past the sync).
        for (int t = tid; t < 4096; t += 256) {
            const int r = t >> 6, c4 = t & 63;
            float4 val = *(const float4*)(v + (size_t)(b * S_ + k0 + r) * HD_ + c4 * 4);
            *(float4*)(Ks + r * 260 + c4 * 4) = val;
        }
        // Online softmax: one thread per row (overlapped with V load above)
        if (tid < 64) {
            const float m_old = Ms[tid];
            float mx = m_old;
            #pragma unroll 8
            for (int j = 0; j < 64; j++) mx = fmaxf(mx, Ps[tid * 64 + j]);
            const float corr = expf(m_old - mx);   // first iter: exp(-inf)=0
            float l = Ls[tid] * corr;
            #pragma unroll 4
            for (int j = 0; j < 64; j++) {
                const float p = expf(Ps[tid * 64 + j] - mx);
                Ps[tid * 64 + j] = p;
                l += p;
            }
            Ms[tid] = mx; Ls[tid] = l; Cr[tid] = corr;
        }
        __syncthreads();

        // Rescale accumulator, then O += P @ V
        float cr[4];
        #pragma unroll
        for (int r = 0; r < 4; r++) cr[r] = Cr[row0 + r];
        #pragma unroll
        for (int r = 0; r < 4; r++)
            #pragma unroll
            for (int c = 0; c < 16; c++) acc[r][c] *= cr[r];

        for (int j = 0; j < 64; j++) {
            float p[4];
            #pragma unroll
            for (int r = 0; r < 4; r++) p[r] = Ps[(row0 + r) * 64 + j];
            #pragma unroll
            for (int c = 0; c < 16; c++) {
                const float vv = Ks[j * 260 + c * 16 + tx];
                #pragma unroll
                for (int r = 0; r < 4; r++)
                    acc[r][c] = fmaf(p[r], vv, acc[r][c]);
            }
        }
    }

    // Epilogue: normalize by row sum, write [b,s, h*HD+d]
    #pragma unroll
    for (int r = 0; r < 4; r++) {
        const float invl = 1.f / Ls[row0 + r];
        #pragma unroll
        for (int c = 0; c < 16; c++) {
            o[(size_t)(b * S_ + q0 + row0 + r) * QKDIM_ + h * HD_ + c * 16 + tx]
                = acc[r][c] * invl;
        }
    }
}

// ---------------------------------------------------------------------------
// Launch: hs -> (Q,K,V GEMMs) -> RoPE -> flash attention -> O GEMM
// Inputs: 0=hidden_states 1=attention_mask(unused; causal computed directly)
//         2=position_ids 3=Wq 4=Wk 5=Wv 6=Wo
// ---------------------------------------------------------------------------
extern "C" void kernel_launch(void* const* d_in, const int* in_sizes, int n_in,
                              void* d_out, int out_size) {
    (void)in_sizes; (void)n_in; (void)out_size;
    const float* hs  = (const float*)d_in[0];
    const int*   pos = (const int*)  d_in[2];
    const float* Wq  = (const float*)d_in[3];
    const float* Wk  = (const float*)d_in[4];
    const float* Wv  = (const float*)d_in[5];
    const float* Wo  = (const float*)d_in[6];
    float* out = (float*)d_out;

    float *gq, *gk, *gv, *ga;
    cudaGetSymbolAddress((void**)&gq, g_q);
    cudaGetSymbolAddress((void**)&gk, g_k);
    cudaGetSymbolAddress((void**)&gv, g_v);
    cudaGetSymbolAddress((void**)&ga, g_att);

    cudaFuncSetAttribute(attn_kernel,
        cudaFuncAttributeMaxDynamicSharedMemorySize, ATTN_SMEM_BYTES);

    // Projections
    sgemm_kernel<<<dim3(QKDIM_ / 128, M_ / 128), 256>>>(hs, Wq, gq, M_, QKDIM_, HID_);
    sgemm_kernel<<<dim3(HD_ / 128,   M_ / 128), 256>>>(hs, Wk, gk, M_, HD_,  HID_);
    sgemm_kernel<<<dim3(HD_ / 128,   M_ / 128), 256>>>(hs, Wv, gv, M_, HD_,  HID_);

    // RoPE on q and k
    {
        const int total = B_ * S_ * NH_ * (HD_ / 2) + B_ * S_ * (HD_ / 2);
        rope_kernel<<<(total + 255) / 256, 256>>>(gq, gk, pos);
    }

    // Attention: grid (qtile, head, batch)
    attn_kernel<<<dim3(S_ / 64, NH_, B_), 256, ATTN_SMEM_BYTES>>>(gq, gk, gv, ga);

    // Output projection
    sgemm_kernel<<<dim3(HID_ / 128, M_ / 128), 256>>>(ga, Wo, out, M_, HID_, HID_);
}

// round 4
// speedup vs baseline: 1.7894x; 1.7894x over previous
#include <cuda_runtime.h>
#include <cuda_bf16.h>
#include <math.h>
#include <stdint.h>

// Problem constants
#define B_ 2
#define S_ 2048
#define HID_ 2048
#define NH_ 8
#define HD_ 256
#define M_ 4096           // B*S
#define QKDIM_ (NH_*HD_)  // 2048

typedef __nv_bfloat16 bf16;

// ---------------------------------------------------------------------------
// Scratch (device globals: allocation-free per harness rules)
// ---------------------------------------------------------------------------
__device__ float g_q[M_ * QKDIM_];   // fp32 Q after proj (pre/post RoPE)
__device__ float g_k[M_ * HD_];
__device__ float g_v[M_ * HD_];

__device__ bf16 g_hsh[M_ * HID_],  g_hsl[M_ * HID_];     // split hidden_states
__device__ bf16 g_qh [M_ * QKDIM_], g_ql [M_ * QKDIM_];  // split Q (post-RoPE)
__device__ bf16 g_kh [M_ * HD_],   g_kl [M_ * HD_];      // split K
__device__ bf16 g_vth[B_ * HD_ * S_], g_vtl[B_ * HD_ * S_]; // V transposed [b][d][s]
__device__ bf16 g_ath[M_ * QKDIM_], g_atl[M_ * QKDIM_];  // split attention output

__device__ bf16 g_wqh[HID_ * QKDIM_], g_wql[HID_ * QKDIM_]; // Wq^T [N][K]
__device__ bf16 g_wkh[HID_ * HD_],    g_wkl[HID_ * HD_];
__device__ bf16 g_wvh[HID_ * HD_],    g_wvl[HID_ * HD_];
__device__ bf16 g_woh[QKDIM_ * HID_], g_wol[QKDIM_ * HID_];

// ---------------------------------------------------------------------------
// Helpers
// ---------------------------------------------------------------------------
__device__ __forceinline__ void split1(float x, bf16& h, bf16& l) {
    h = __float2bfloat16(x);
    l = __float2bfloat16(x - __bfloat162float(h));
}

__device__ __forceinline__ void mma16816(float (&d)[4], const uint32_t (&a)[4],
                                         uint32_t b0, uint32_t b1) {
    asm volatile(
        "mma.sync.aligned.m16n8k16.row.col.f32.bf16.bf16.f32 "
        "{%0,%1,%2,%3}, {%4,%5,%6,%7}, {%8,%9}, {%0,%1,%2,%3};\n"
        : "+f"(d[0]), "+f"(d[1]), "+f"(d[2]), "+f"(d[3])
        : "r"(a[0]), "r"(a[1]), "r"(a[2]), "r"(a[3]), "r"(b0), "r"(b1));
}

// ---------------------------------------------------------------------------
// Elementwise split: fp32 -> (hi, lo) bf16.  n multiple of 4.
// ---------------------------------------------------------------------------
__global__ void split_kernel(const float* __restrict__ in,
                             bf16* __restrict__ oh, bf16* __restrict__ ol, int n) {
    int i = (blockIdx.x * blockDim.x + threadIdx.x) * 4;
    if (i >= n) return;
    float4 v = *(const float4*)(in + i);
    bf16 h0,l0,h1,l1,h2,l2,h3,l3;
    split1(v.x,h0,l0); split1(v.y,h1,l1); split1(v.z,h2,l2); split1(v.w,h3,l3);
    __nv_bfloat162 a, b;
    a.x=h0; a.y=h1; b.x=h2; b.y=h3;
    *(__nv_bfloat162*)(oh+i)   = a; *(__nv_bfloat162*)(oh+i+2) = b;
    a.x=l0; a.y=l1; b.x=l2; b.y=l3;
    *(__nv_bfloat162*)(ol+i)   = a; *(__nv_bfloat162*)(ol+i+2) = b;
}

// ---------------------------------------------------------------------------
// Tiled transpose + split: in [R][C] fp32 (batched, z) -> out [C][R] bf16 hi/lo.
// R, C multiples of 32.  block (32,8).
// ---------------------------------------------------------------------------
__global__ void transpose_split_kernel(const float* __restrict__ in,
                                       bf16* __restrict__ oh, bf16* __restrict__ ol,
                                       int R, int C) {
    __shared__ float t[32][33];
    const size_t bo = (size_t)blockIdx.z * R * C;
    const float* ip = in + bo;
    bf16* ohp = oh + bo;
    bf16* olp = ol + bo;
    const int r0 = blockIdx.y * 32, c0 = blockIdx.x * 32;
    #pragma unroll
    for (int i = 0; i < 4; i++) {
        int r = threadIdx.y + i * 8;
        t[r][threadIdx.x] = ip[(size_t)(r0 + r) * C + c0 + threadIdx.x];
    }
    __syncthreads();
    #pragma unroll
    for (int i = 0; i < 4; i++) {
        int c = threadIdx.y + i * 8;              // output row = original col
        float v = t[threadIdx.x][c];
        bf16 h, l; split1(v, h, l);
        size_t o = (size_t)(c0 + c) * R + r0 + threadIdx.x;
        ohp[o] = h; olp[o] = l;
    }
}

// ---------------------------------------------------------------------------
// GEMM: C[M,N] = A[M,K] @ B[K,N], with A given as split bf16 row-major [M][K]
// and B given as split bf16 TRANSPOSED [N][K].  3-MMA bf16 split, fp32 accum.
// 128x128 tile, BK=32, 256 threads (8 warps: 4x2 of 32x64).
// ---------------------------------------------------------------------------
#define GLDA 40   // 32 + 8 halves pad
__global__ __launch_bounds__(256) void gemm_bf16s(
    const bf16* __restrict__ Ah, const bf16* __restrict__ Al,
    const bf16* __restrict__ Bh, const bf16* __restrict__ Bl,
    float* __restrict__ C, int M, int N, int K)
{
    __shared__ bf16 sAh[128][GLDA], sAl[128][GLDA];
    __shared__ bf16 sBh[128][GLDA], sBl[128][GLDA];

    const int tid = threadIdx.x;
    const int wid = tid >> 5, lane = tid & 31;
    const int g = lane >> 2, tg = lane & 3;
    const int wm = (wid & 3) * 32;
    const int wn = (wid >> 2) * 64;
    const int row0 = blockIdx.y * 128;
    const int col0 = blockIdx.x * 128;

    float c[2][8][4] = {};

    for (int k0 = 0; k0 < K; k0 += 32) {
        #pragma unroll
        for (int i = 0; i < 2; i++) {
            int idx = tid * 2 + i;         // 0..511
            int r = idx >> 2;              // 0..127
            int cc = (idx & 3) * 8;        // 0,8,16,24
            *(uint4*)&sAh[r][cc] = *(const uint4*)(Ah + (size_t)(row0 + r) * K + k0 + cc);
            *(uint4*)&sAl[r][cc] = *(const uint4*)(Al + (size_t)(row0 + r) * K + k0 + cc);
            *(uint4*)&sBh[r][cc] = *(const uint4*)(Bh + (size_t)(col0 + r) * K + k0 + cc);
            *(uint4*)&sBl[r][cc] = *(const uint4*)(Bl + (size_t)(col0 + r) * K + k0 + cc);
        }
        __syncthreads();
        #pragma unroll
        for (int kk = 0; kk < 32; kk += 16) {
            uint32_t ah[2][4], al[2][4];
            #pragma unroll
            for (int mt = 0; mt < 2; mt++) {
                int r = wm + mt * 16 + g;
                ah[mt][0] = *(const uint32_t*)&sAh[r    ][kk + tg*2];
                ah[mt][1] = *(const uint32_t*)&sAh[r + 8][kk + tg*2];
                ah[mt][2] = *(const uint32_t*)&sAh[r    ][kk + tg*2 + 8];
                ah[mt][3] = *(const uint32_t*)&sAh[r + 8][kk + tg*2 + 8];
                al[mt][0] = *(const uint32_t*)&sAl[r    ][kk + tg*2];
                al[mt][1] = *(const uint32_t*)&sAl[r + 8][kk + tg*2];
                al[mt][2] = *(const uint32_t*)&sAl[r    ][kk + tg*2 + 8];
                al[mt][3] = *(const uint32_t*)&sAl[r + 8][kk + tg*2 + 8];
            }
            #pragma unroll
            for (int nt = 0; nt < 8; nt++) {
                int cn = wn + nt * 8 + g;
                uint32_t bh0 = *(const uint32_t*)&sBh[cn][kk + tg*2];
                uint32_t bh1 = *(const uint32_t*)&sBh[cn][kk + tg*2 + 8];
                uint32_t bl0 = *(const uint32_t*)&sBl[cn][kk + tg*2];
                uint32_t bl1 = *(const uint32_t*)&sBl[cn][kk + tg*2 + 8];
                #pragma unroll
                for (int mt = 0; mt < 2; mt++) {
                    mma16816(c[mt][nt], ah[mt], bh0, bh1);
                    mma16816(c[mt][nt], ah[mt], bl0, bl1);
                    mma16816(c[mt][nt], al[mt], bh0, bh1);
                }
            }
        }
        __syncthreads();
    }

    #pragma unroll
    for (int mt = 0; mt < 2; mt++)
        #pragma unroll
        for (int nt = 0; nt < 8; nt++) {
            int r  = row0 + wm + mt * 16 + g;
            int cn = col0 + wn + nt * 8 + tg * 2;
            float2 v01; v01.x = c[mt][nt][0]; v01.y = c[mt][nt][1];
            float2 v23; v23.x = c[mt][nt][2]; v23.y = c[mt][nt][3];
            *(float2*)(C + (size_t)r * N + cn)       = v01;
            *(float2*)(C + (size_t)(r + 8) * N + cn) = v23;
        }
}

// ---------------------------------------------------------------------------
// RoPE (in-place on fp32 q and k).
// ---------------------------------------------------------------------------
__global__ void rope_kernel(float* __restrict__ q, float* __restrict__ k,
                            const int* __restrict__ pos)
{
    const int QP = B_ * S_ * NH_ * (HD_ / 2);
    const int KP = B_ * S_ * (HD_ / 2);
    int idx = blockIdx.x * blockDim.x + threadIdx.x;
    if (idx >= QP + KP) return;
    const float L2B = 13.28771237954945f;  // log2(10000)
    if (idx < QP) {
        const int i  = idx & 127;
        const int h  = (idx >> 7) & 7;
        const int bs = idx >> 10;
        const float inv = exp2f(-(float)(2 * i) * (L2B / 256.f));
        const float ang = (float)pos[bs] * inv;
        float sn, cs; sincosf(ang, &sn, &cs);
        float* base = q + (size_t)bs * QKDIM_ + h * HD_;
        const float x1 = base[i], x2 = base[i + 128];
        base[i]       = x1 * cs - x2 * sn;
        base[i + 128] = x2 * cs + x1 * sn;
    } else {
        const int j  = idx - QP;
        const int i  = j & 127;
        const int bs = j >> 7;
        const float inv = exp2f(-(float)(2 * i) * (L2B / 256.f));
        const float ang = (float)pos[bs] * inv;
        float sn, cs; sincosf(ang, &sn, &cs);
        float* base = k + (size_t)bs * HD_;
        const float x1 = base[i], x2 = base[i + 128];
        base[i]       = x1 * cs - x2 * sn;
        base[i + 128] = x2 * cs + x1 * sn;
    }
}

// ---------------------------------------------------------------------------
// Flash attention with bf16-split MMAs. CTA = (qtile(64), head, batch),
// 256 threads = 8 warps. Warp w: rows (w&3)*16.
//   S-phase:  cols (w>>2)*32   (4 n8-tiles),  k = 256 dims
//   PV-phase: dims (w>>2)*128  (16 n8-tiles), k = 64 keys
// K tile and V tile share one SMEM region (V is dim-major [256][64]).
// ---------------------------------------------------------------------------
#define AQ_LD 264    // 256 + 8 halves
#define AP_LD 72     // 64 + 8 halves
#define APS_LD 67    // floats
#define AKV_HALVES 18432   // max(64*264, 256*72)

#define ATT_SMEM_BYTES ((64*AQ_LD*2 + AKV_HALVES*2 + 64*AP_LD*2) * 2 + (64*APS_LD + 3*64) * 4)

__global__ __launch_bounds__(256, 1) void attn_mma_kernel(
    const bf16* __restrict__ qh, const bf16* __restrict__ ql,
    const bf16* __restrict__ kh, const bf16* __restrict__ kl,
    const bf16* __restrict__ vth, const bf16* __restrict__ vtl,
    bf16* __restrict__ ath, bf16* __restrict__ atl)
{
    extern __shared__ char smraw[];
    bf16* Qh  = (bf16*)smraw;
    bf16* Ql  = Qh  + 64 * AQ_LD;
    bf16* KVh = Ql  + 64 * AQ_LD;
    bf16* KVl = KVh + AKV_HALVES;
    bf16* Ph  = KVl + AKV_HALVES;
    bf16* Pl  = Ph  + 64 * AP_LD;
    float* Ps = (float*)(Pl + 64 * AP_LD);
    float* Ms = Ps + 64 * APS_LD;
    float* Ls = Ms + 64;
    float* Cr = Ls + 64;

    const int qt = (int)gridDim.x - 1 - (int)blockIdx.x;  // heavy tiles first
    const int h  = blockIdx.y;
    const int b  = blockIdx.z;
    const int tid = threadIdx.x;
    const int wid = tid >> 5, lane = tid & 31;
    const int g = lane >> 2, tg = lane & 3;
    const int wm  = (wid & 3) * 16;
    const int wn2 = (wid >> 2) * 32;
    const int wd  = (wid >> 2) * 128;
    const int q0 = qt * 64;
    const float scale = 0.0625f;

    // Load Q tile [64][256] split
    for (int i = tid; i < 2048; i += 256) {
        int r = i >> 5, cc = (i & 31) * 8;
        size_t go = (size_t)(b * S_ + q0 + r) * QKDIM_ + h * HD_ + cc;
        *(uint4*)&Qh[r * AQ_LD + cc] = *(const uint4*)(qh + go);
        *(uint4*)&Ql[r * AQ_LD + cc] = *(const uint4*)(ql + go);
    }
    if (tid < 64) { Ms[tid] = -INFINITY; Ls[tid] = 0.f; Cr[tid] = 0.f; }

    float oc[16][4] = {};

    for (int kt = 0; kt <= qt; ++kt) {
        const int k0 = kt * 64;
        __syncthreads();

        // Load K tile [64 keys][256 dims] split into KV region (stride AQ_LD)
        for (int i = tid; i < 2048; i += 256) {
            int r = i >> 5, cc = (i & 31) * 8;
            size_t go = (size_t)(b * S_ + k0 + r) * HD_ + cc;
            *(uint4*)&KVh[r * AQ_LD + cc] = *(const uint4*)(kh + go);
            *(uint4*)&KVl[r * AQ_LD + cc] = *(const uint4*)(kl + go);
        }
        __syncthreads();

        // S = Q @ K^T via 3-MMA split
        float sc[4][4] = {};
        #pragma unroll
        for (int kk = 0; kk < 256; kk += 16) {
            uint32_t ah[4], al[4];
            {
                int ra = (wm + g) * AQ_LD + kk + tg * 2;
                ah[0] = *(const uint32_t*)&Qh[ra];
                ah[1] = *(const uint32_t*)&Qh[ra + 8 * AQ_LD];
                ah[2] = *(const uint32_t*)&Qh[ra + 8];
                ah[3] = *(const uint32_t*)&Qh[ra + 8 * AQ_LD + 8];
                al[0] = *(const uint32_t*)&Ql[ra];
                al[1] = *(const uint32_t*)&Ql[ra + 8 * AQ_LD];
                al[2] = *(const uint32_t*)&Ql[ra + 8];
                al[3] = *(const uint32_t*)&Ql[ra + 8 * AQ_LD + 8];
            }
            #pragma unroll
            for (int nt = 0; nt < 4; nt++) {
                int kb = (wn2 + nt * 8 + g) * AQ_LD + kk + tg * 2;
                uint32_t bh0 = *(const uint32_t*)&KVh[kb];
                uint32_t bh1 = *(const uint32_t*)&KVh[kb + 8];
                uint32_t bl0 = *(const uint32_t*)&KVl[kb];
                uint32_t bl1 = *(const uint32_t*)&KVl[kb + 8];
                mma16816(sc[nt], ah, bh0, bh1);
                mma16816(sc[nt], ah, bl0, bl1);
                mma16816(sc[nt], al, bh0, bh1);
            }
        }

        // Scale + causal mask; store S to Ps
        #pragma unroll
        for (int nt = 0; nt < 4; nt++) {
            int colL = wn2 + nt * 8 + tg * 2;       // local col in tile
            int col  = k0 + colL;                    // global key index
            int r0g  = q0 + wm + g;
            int r1g  = r0g + 8;
            float s0 = sc[nt][0] * scale; if (col     > r0g) s0 = -1e30f;
            float s1 = sc[nt][1] * scale; if (col + 1 > r0g) s1 = -1e30f;
            float s2 = sc[nt][2] * scale; if (col     > r1g) s2 = -1e30f;
            float s3 = sc[nt][3] * scale; if (col + 1 > r1g) s3 = -1e30f;
            int pr = (wm + g) * APS_LD + colL;
            Ps[pr]                  = s0;
            Ps[pr + 1]              = s1;
            Ps[pr + 8 * APS_LD]     = s2;
            Ps[pr + 8 * APS_LD + 1] = s3;
        }
        __syncthreads();

        // Threads <64: online softmax per row -> Ph/Pl (split bf16).
        // Threads >=64: load V tile (dim-major [256][64]) into KV region.
        if (tid < 64) {
            const float m_old = Ms[tid];
            float mx = m_old;
            const float* pr = Ps + tid * APS_LD;
            #pragma unroll 8
            for (int j = 0; j < 64; j++) mx = fmaxf(mx, pr[j]);
            const float corr = (m_old == -INFINITY) ? 0.f : __expf(m_old - mx);
            float l = Ls[tid] * corr;
            #pragma unroll 4
            for (int j = 0; j < 64; j++) {
                const float p = __expf(pr[j] - mx);
                bf16 hb, lb; split1(p, hb, lb);
                Ph[tid * AP_LD + j] = hb;
                Pl[tid * AP_LD + j] = lb;
                l += p;
            }
            Ms[tid] = mx; Ls[tid] = l; Cr[tid] = corr;
        } else {
            for (int i = tid - 64; i < 2048; i += 192) {
                int r = i >> 3, cc = (i & 7) * 8;
                size_t go = (size_t)b * HD_ * S_ + (size_t)r * S_ + k0 + cc;
                *(uint4*)&KVh[r * AP_LD + cc] = *(const uint4*)(vth + go);
                *(uint4*)&KVl[r * AP_LD + cc] = *(const uint4*)(vtl + go);
            }
        }
        __syncthreads();

        // Rescale accumulator, then O += P @ V (3-MMA split)
        const float cr0 = Cr[wm + g], cr1 = Cr[wm + g + 8];
        #pragma unroll
        for (int nt = 0; nt < 16; nt++) {
            oc[nt][0] *= cr0; oc[nt][1] *= cr0;
            oc[nt][2] *= cr1; oc[nt][3] *= cr1;
        }
        #pragma unroll
        for (int kk = 0; kk < 64; kk += 16) {
            uint32_t pa[4], pl_[4];
            {
                int ra = (wm + g) * AP_LD + kk + tg * 2;
                pa[0]  = *(const uint32_t*)&Ph[ra];
                pa[1]  = *(const uint32_t*)&Ph[ra + 8 * AP_LD];
                pa[2]  = *(const uint32_t*)&Ph[ra + 8];
                pa[3]  = *(const uint32_t*)&Ph[ra + 8 * AP_LD + 8];
                pl_[0] = *(const uint32_t*)&Pl[ra];
                pl_[1] = *(const uint32_t*)&Pl[ra + 8 * AP_LD];
                pl_[2] = *(const uint32_t*)&Pl[ra + 8];
                pl_[3] = *(const uint32_t*)&Pl[ra + 8 * AP_LD + 8];
            }
            #pragma unroll
            for (int nt = 0; nt < 16; nt++) {
                int kb = (wd + nt * 8 + g) * AP_LD + kk + tg * 2;
                uint32_t bh0 = *(const uint32_t*)&KVh[kb];
                uint32_t bh1 = *(const uint32_t*)&KVh[kb + 8];
                uint32_t bl0 = *(const uint32_t*)&KVl[kb];
                uint32_t bl1 = *(const uint32_t*)&KVl[kb + 8];
                mma16816(oc[nt], pa,  bh0, bh1);
                mma16816(oc[nt], pa,  bl0, bl1);
                mma16816(oc[nt], pl_, bh0, bh1);
            }
        }
    }

    // Epilogue: normalize, split to bf16, write [b,s, h*HD+d]
    const float inv0 = 1.f / Ls[wm + g];
    const float inv1 = 1.f / Ls[wm + g + 8];
    #pragma unroll
    for (int nt = 0; nt < 16; nt++) {
        int d = wd + nt * 8 + tg * 2;
        size_t base0 = (size_t)(b * S_ + q0 + wm + g) * QKDIM_ + h * HD_ + d;
        size_t base1 = base0 + 8 * QKDIM_;
        float v0 = oc[nt][0] * inv0, v1 = oc[nt][1] * inv0;
        float v2 = oc[nt][2] * inv1, v3 = oc[nt][3] * inv1;
        bf16 h0,l0,h1,l1,h2,l2,h3,l3;
        split1(v0,h0,l0); split1(v1,h1,l1); split1(v2,h2,l2); split1(v3,h3,l3);
        __nv_bfloat162 t;
        t.x=h0; t.y=h1; *(__nv_bfloat162*)(ath + base0) = t;
        t.x=l0; t.y=l1; *(__nv_bfloat162*)(atl + base0) = t;
        t.x=h2; t.y=h3; *(__nv_bfloat162*)(ath + base1) = t;
        t.x=l2; t.y=l3; *(__nv_bfloat162*)(atl + base1) = t;
    }
}

// ---------------------------------------------------------------------------
// Launch
// Inputs: 0=hidden_states 1=attention_mask(unused) 2=position_ids
//         3=Wq 4=Wk 5=Wv 6=Wo
// ---------------------------------------------------------------------------
extern "C" void kernel_launch(void* const* d_in, const int* in_sizes, int n_in,
                              void* d_out, int out_size) {
    (void)in_sizes; (void)n_in; (void)out_size;
    const float* hs  = (const float*)d_in[0];
    const int*   pos = (const int*)  d_in[2];
    const float* Wq  = (const float*)d_in[3];
    const float* Wk  = (const float*)d_in[4];
    const float* Wv  = (const float*)d_in[5];
    const float* Wo  = (const float*)d_in[6];
    float* out = (float*)d_out;

    float *gq, *gk, *gv;
    bf16 *hsh,*hsl,*qh,*ql,*kh,*kl,*vth,*vtl,*ath,*atl;
    bf16 *wqh,*wql,*wkh,*wkl,*wvh,*wvl,*woh,*wol;
    cudaGetSymbolAddress((void**)&gq, g_q);
    cudaGetSymbolAddress((void**)&gk, g_k);
    cudaGetSymbolAddress((void**)&gv, g_v);
    cudaGetSymbolAddress((void**)&hsh, g_hsh); cudaGetSymbolAddress((void**)&hsl, g_hsl);
    cudaGetSymbolAddress((void**)&qh,  g_qh);  cudaGetSymbolAddress((void**)&ql,  g_ql);
    cudaGetSymbolAddress((void**)&kh,  g_kh);  cudaGetSymbolAddress((void**)&kl,  g_kl);
    cudaGetSymbolAddress((void**)&vth, g_vth); cudaGetSymbolAddress((void**)&vtl, g_vtl);
    cudaGetSymbolAddress((void**)&ath, g_ath); cudaGetSymbolAddress((void**)&atl, g_atl);
    cudaGetSymbolAddress((void**)&wqh, g_wqh); cudaGetSymbolAddress((void**)&wql, g_wql);
    cudaGetSymbolAddress((void**)&wkh, g_wkh); cudaGetSymbolAddress((void**)&wkl, g_wkl);
    cudaGetSymbolAddress((void**)&wvh, g_wvh); cudaGetSymbolAddress((void**)&wvl, g_wvl);
    cudaGetSymbolAddress((void**)&woh, g_woh); cudaGetSymbolAddress((void**)&wol, g_wol);

    cudaFuncSetAttribute(attn_mma_kernel,
        cudaFuncAttributeMaxDynamicSharedMemorySize, ATT_SMEM_BYTES);

    const dim3 tb(32, 8);

    // Split hidden states; transpose+split weights
    split_kernel<<<(M_ * HID_ / 4 + 255) / 256, 256>>>(hs, hsh, hsl, M_ * HID_);
    transpose_split_kernel<<<dim3(QKDIM_/32, HID_/32, 1), tb>>>(Wq, wqh, wql, HID_, QKDIM_);
    transpose_split_kernel<<<dim3(HD_/32,    HID_/32, 1), tb>>>(Wk, wkh, wkl, HID_, HD_);
    transpose_split_kernel<<<dim3(HD_/32,    HID_/32, 1), tb>>>(Wv, wvh, wvl, HID_, HD_);
    transpose_split_kernel<<<dim3(HID_/32, QKDIM_/32, 1), tb>>>(Wo, woh, wol, QKDIM_, HID_);

    // Projections (tensor core)
    gemm_bf16s<<<dim3(QKDIM_/128, M_/128), 256>>>(hsh, hsl, wqh, wql, gq, M_, QKDIM_, HID_);
    gemm_bf16s<<<dim3(HD_/128,   M_/128), 256>>>(hsh, hsl, wkh, wkl, gk, M_, HD_,  HID_);
    gemm_bf16s<<<dim3(HD_/128,   M_/128), 256>>>(hsh, hsl, wvh, wvl, gv, M_, HD_,  HID_);

    // RoPE (fp32)
    {
        const int total = B_ * S_ * NH_ * (HD_ / 2) + B_ * S_ * (HD_ / 2);
        rope_kernel<<<(total + 255) / 256, 256>>>(gq, gk, pos);
    }

    // Split Q/K; transpose+split V per batch ([2048][256] -> [256][2048])
    split_kernel<<<(M_ * QKDIM_ / 4 + 255) / 256, 256>>>(gq, qh, ql, M_ * QKDIM_);
    split_kernel<<<(M_ * HD_   / 4 + 255) / 256, 256>>>(gk, kh, kl, M_ * HD_);
    transpose_split_kernel<<<dim3(HD_/32, S_/32, B_), tb>>>(gv, vth, vtl, S_, HD_);

    // Attention (tensor core flash)
    attn_mma_kernel<<<dim3(S_/64, NH_, B_), 256, ATT_SMEM_BYTES>>>(
        qh, ql, kh, kl, vth, vtl, ath, atl);

    // Output projection (tensor core)
    gemm_bf16s<<<dim3(HID_/128, M_/128), 256>>>(ath, atl, woh, wol, out, M_, HID_, HID_);
}

// round 6
// speedup vs baseline: 2.3858x; 1.3332x over previous
#include <cuda_runtime.h>
#include <cuda_bf16.h>
#include <math.h>
#include <stdint.h>

// Problem constants
#define B_ 2
#define S_ 2048
#define HID_ 2048
#define NH_ 8
#define HD_ 256
#define M_ 4096           // B*S
#define QKDIM_ (NH_*HD_)  // 2048
#define NQKV_ 2560        // 2048 (Q) + 256 (K) + 256 (V)

typedef __nv_bfloat16 bf16;

// ---------------------------------------------------------------------------
// Scratch (device globals: allocation-free per harness rules)
// ---------------------------------------------------------------------------
__device__ float g_qkv[M_ * NQKV_];                         // fused QKV output (fp32)

__device__ bf16 g_hsh[M_ * HID_],  g_hsl[M_ * HID_];        // split hidden_states
__device__ bf16 g_qh [M_ * QKDIM_], g_ql [M_ * QKDIM_];     // split Q (post-RoPE)
__device__ bf16 g_kh [M_ * HD_],   g_kl [M_ * HD_];         // split K
__device__ bf16 g_vth[B_ * HD_ * S_], g_vtl[B_ * HD_ * S_]; // V transposed [b][d][s]
__device__ bf16 g_ath[M_ * QKDIM_], g_atl[M_ * QKDIM_];     // split attention output

__device__ bf16 g_wallh[NQKV_ * HID_];                      // fused [Wq;Wk;Wv]^T hi
__device__ bf16 g_walll[NQKV_ * HID_];                      // fused lo
__device__ bf16 g_woh[QKDIM_ * HID_], g_wol[QKDIM_ * HID_];

// ---------------------------------------------------------------------------
// Helpers
// ---------------------------------------------------------------------------
__device__ __forceinline__ void split1(float x, bf16& h, bf16& l) {
    h = __float2bfloat16(x);
    l = __float2bfloat16(x - __bfloat162float(h));
}

__device__ __forceinline__ void mma16816(float (&d)[4], const uint32_t (&a)[4],
                                         uint32_t b0, uint32_t b1) {
    asm volatile(
        "mma.sync.aligned.m16n8k16.row.col.f32.bf16.bf16.f32 "
        "{%0,%1,%2,%3}, {%4,%5,%6,%7}, {%8,%9}, {%0,%1,%2,%3};\n"
        : "+f"(d[0]), "+f"(d[1]), "+f"(d[2]), "+f"(d[3])
        : "r"(a[0]), "r"(a[1]), "r"(a[2]), "r"(a[3]), "r"(b0), "r"(b1));
}

__device__ __forceinline__ void ldsm_x4(uint32_t (&r)[4], const bf16* p) {
    uint32_t a = (uint32_t)__cvta_generic_to_shared(p);
    asm volatile("ldmatrix.sync.aligned.m8n8.x4.shared.b16 {%0,%1,%2,%3}, [%4];\n"
        : "=r"(r[0]), "=r"(r[1]), "=r"(r[2]), "=r"(r[3]) : "r"(a));
}

__device__ __forceinline__ void cpasync16(bf16* s, const bf16* g) {
    uint32_t sa = (uint32_t)__cvta_generic_to_shared(s);
    asm volatile("cp.async.cg.shared.global [%0], [%1], 16;\n" :: "r"(sa), "l"(g));
}
__device__ __forceinline__ void cpcommit() {
    asm volatile("cp.async.commit_group;\n");
}
template<int N> __device__ __forceinline__ void cpwait() {
    asm volatile("cp.async.wait_group %0;\n" :: "n"(N));
}

// ---------------------------------------------------------------------------
// Elementwise split with strided source: out[i] for i over rows*2^colshift,
// src = in[(i>>colshift)*ldin + (i & mask)].
// ---------------------------------------------------------------------------
__global__ void split_strided_kernel(const float* __restrict__ in,
                                     bf16* __restrict__ oh, bf16* __restrict__ ol,
                                     int n, int colshift, int ldin) {
    int i = (blockIdx.x * blockDim.x + threadIdx.x) * 4;
    if (i >= n) return;
    int r = i >> colshift;
    int c = i & ((1 << colshift) - 1);
    float4 v = *(const float4*)(in + (size_t)r * ldin + c);
    bf16 h0,l0,h1,l1,h2,l2,h3,l3;
    split1(v.x,h0,l0); split1(v.y,h1,l1); split1(v.z,h2,l2); split1(v.w,h3,l3);
    __nv_bfloat162 a, b;
    a.x=h0; a.y=h1; b.x=h2; b.y=h3;
    *(__nv_bfloat162*)(oh+i)   = a; *(__nv_bfloat162*)(oh+i+2) = b;
    a.x=l0; a.y=l1; b.x=l2; b.y=l3;
    *(__nv_bfloat162*)(ol+i)   = a; *(__nv_bfloat162*)(ol+i+2) = b;
}

// ---------------------------------------------------------------------------
// Tiled transpose + split: in[r][c] (ldin, batch bsIn) -> out[c][r] (ldout, bsOut)
// 32x32 tiles, block (32,8).
// ---------------------------------------------------------------------------
__global__ void transpose_split_kernel(const float* __restrict__ in,
                                       bf16* __restrict__ oh, bf16* __restrict__ ol,
                                       int ldin, size_t bsIn, int ldout, size_t bsOut) {
    __shared__ float t[32][33];
    const float* ip = in + (size_t)blockIdx.z * bsIn;
    bf16* ohp = oh + (size_t)blockIdx.z * bsOut;
    bf16* olp = ol + (size_t)blockIdx.z * bsOut;
    const int r0 = blockIdx.y * 32, c0 = blockIdx.x * 32;
    #pragma unroll
    for (int i = 0; i < 4; i++) {
        int r = threadIdx.y + i * 8;
        t[r][threadIdx.x] = ip[(size_t)(r0 + r) * ldin + c0 + threadIdx.x];
    }
    __syncthreads();
    #pragma unroll
    for (int i = 0; i < 4; i++) {
        int c = threadIdx.y + i * 8;
        float v = t[threadIdx.x][c];
        bf16 h, l; split1(v, h, l);
        size_t o = (size_t)(c0 + c) * ldout + r0 + threadIdx.x;
        ohp[o] = h; olp[o] = l;
    }
}

// ---------------------------------------------------------------------------
// GEMM: C[M,N] = A[M,K] @ B^T where A split bf16 [M][K], B split bf16 [N][K].
// 128x128 tile, BK=32, 256 threads (8 warps 4x2, warp tile 32x64).
// 2-stage cp.async pipeline + ldmatrix fragments + 3-MMA bf16 split.
// ---------------------------------------------------------------------------
#define GLDA 40                 // 32 + 8 halves pad (80B row: LDSM conflict-free)
#define PLANE (128 * GLDA)      // halves per plane
// planes per stage: Ah, Al, Bh, Bl (4). stages: 2. total = 8 planes.
#define GEMM_SMEM (8 * PLANE * 2)   // bytes: 8 * 5120 * 2 = 81920

__global__ __launch_bounds__(256) void gemm_bf16s(
    const bf16* __restrict__ Ah, const bf16* __restrict__ Al,
    const bf16* __restrict__ Bh, const bf16* __restrict__ Bl,
    float* __restrict__ C, int M, int N, int K)
{
    extern __shared__ bf16 sm[];
    const int tid = threadIdx.x;
    const int wid = tid >> 5, lane = tid & 31;
    const int g = lane >> 2, tg = lane & 3;
    const int m8 = lane >> 3, ri = lane & 7;     // ldmatrix lane decomposition
    const int wm = (wid & 3) * 32;
    const int wn = (wid >> 2) * 64;
    const int row0 = blockIdx.y * 128;
    const int col0 = blockIdx.x * 128;

    // cp.async mapping: thread -> row tid>>1, halves col (tid&1)*16 (two 16B chunks)
    const int lr = tid >> 1;
    const int lc = (tid & 1) * 16;
    const bf16* gA  = Ah + (size_t)(row0 + lr) * K + lc;
    const bf16* gAl = Al + (size_t)(row0 + lr) * K + lc;
    const bf16* gB  = Bh + (size_t)(col0 + lr) * K + lc;
    const bf16* gBl = Bl + (size_t)(col0 + lr) * K + lc;
    const int soff = lr * GLDA + lc;

    float acc[2][8][4] = {};

    const int nk = K / 32;

    // prologue: stage 0
    {
        bf16* s = sm + soff;
        cpasync16(s,             gA);      cpasync16(s + 8,             gA + 8);
        cpasync16(s + PLANE,     gAl);     cpasync16(s + PLANE + 8,     gAl + 8);
        cpasync16(s + 2*PLANE,   gB);      cpasync16(s + 2*PLANE + 8,   gB + 8);
        cpasync16(s + 3*PLANE,   gBl);     cpasync16(s + 3*PLANE + 8,   gBl + 8);
        cpcommit();
    }

    for (int i = 0; i < nk; i++) {
        if (i + 1 < nk) {
            const int k0 = (i + 1) * 32;
            bf16* s = sm + ((i + 1) & 1) * 4 * PLANE + soff;
            cpasync16(s,           gA + k0);   cpasync16(s + 8,           gA + k0 + 8);
            cpasync16(s + PLANE,   gAl + k0);  cpasync16(s + PLANE + 8,   gAl + k0 + 8);
            cpasync16(s + 2*PLANE, gB + k0);   cpasync16(s + 2*PLANE + 8, gB + k0 + 8);
            cpasync16(s + 3*PLANE, gBl + k0);  cpasync16(s + 3*PLANE + 8, gBl + k0 + 8);
            cpcommit();
            cpwait<1>();
        } else {
            cpwait<0>();
        }
        __syncthreads();

        const bf16* pAh = sm + (i & 1) * 4 * PLANE;
        const bf16* pAl = pAh + PLANE;
        const bf16* pBh = pAh + 2 * PLANE;
        const bf16* pBl = pAh + 3 * PLANE;

        #pragma unroll
        for (int kk = 0; kk < 32; kk += 16) {
            uint32_t ah[2][4], al[2][4];
            #pragma unroll
            for (int mt = 0; mt < 2; mt++) {
                const int ao = (wm + mt * 16 + (m8 & 1) * 8 + ri) * GLDA + kk + (m8 >> 1) * 8;
                ldsm_x4(ah[mt], pAh + ao);
                ldsm_x4(al[mt], pAl + ao);
            }
            uint32_t bh[4][4], bl[4][4];
            #pragma unroll
            for (int p = 0; p < 4; p++) {
                const int bo = (wn + p * 16 + (m8 >> 1) * 8 + ri) * GLDA + kk + (m8 & 1) * 8;
                ldsm_x4(bh[p], pBh + bo);
                ldsm_x4(bl[p], pBl + bo);
            }
            #pragma unroll
            for (int p = 0; p < 4; p++)
                #pragma unroll
                for (int sub = 0; sub < 2; sub++) {
                    const int nt = p * 2 + sub;
                    const uint32_t h0 = bh[p][sub*2], h1 = bh[p][sub*2+1];
                    const uint32_t l0 = bl[p][sub*2], l1 = bl[p][sub*2+1];
                    #pragma unroll
                    for (int mt = 0; mt < 2; mt++) {
                        mma16816(acc[mt][nt], ah[mt], h0, h1);
                        mma16816(acc[mt][nt], ah[mt], l0, l1);
                        mma16816(acc[mt][nt], al[mt], h0, h1);
                    }
                }
        }
        __syncthreads();
    }

    #pragma unroll
    for (int mt = 0; mt < 2; mt++)
        #pragma unroll
        for (int nt = 0; nt < 8; nt++) {
            const int r  = row0 + wm + mt * 16 + g;
            const int cn = col0 + wn + nt * 8 + tg * 2;
            float2 v01; v01.x = acc[mt][nt][0]; v01.y = acc[mt][nt][1];
            float2 v23; v23.x = acc[mt][nt][2]; v23.y = acc[mt][nt][3];
            *(float2*)(C + (size_t)r * N + cn)       = v01;
            *(float2*)(C + (size_t)(r + 8) * N + cn) = v23;
        }
}

// ---------------------------------------------------------------------------
// RoPE in-place on fused QKV buffer [M][2560]: Q at cols h*256, K at col 2048.
// ---------------------------------------------------------------------------
__global__ void rope_kernel(float* __restrict__ qkv, const int* __restrict__ pos)
{
    const int QP = B_ * S_ * NH_ * (HD_ / 2);
    const int KP = B_ * S_ * (HD_ / 2);
    int idx = blockIdx.x * blockDim.x + threadIdx.x;
    if (idx >= QP + KP) return;
    const float L2B = 13.28771237954945f;  // log2(10000)
    int i, bs; float* base;
    if (idx < QP) {
        i  = idx & 127;
        const int h = (idx >> 7) & 7;
        bs = idx >> 10;
        base = qkv + (size_t)bs * NQKV_ + h * HD_;
    } else {
        const int j = idx - QP;
        i  = j & 127;
        bs = j >> 7;
        base = qkv + (size_t)bs * NQKV_ + QKDIM_;
    }
    const float inv = exp2f(-(float)(2 * i) * (L2B / 256.f));
    const float ang = (float)pos[bs] * inv;
    float sn, cs; sincosf(ang, &sn, &cs);
    const float x1 = base[i], x2 = base[i + 128];
    base[i]       = x1 * cs - x2 * sn;
    base[i + 128] = x2 * cs + x1 * sn;
}

// ---------------------------------------------------------------------------
// Flash attention, bf16-split MMAs + ldmatrix + cp.async tile loads.
// CTA = (qtile(64), head, batch), 256 threads = 8 warps.
//   S-phase:  warp (w&3) rows 16, (w>>2) col-group 32; k = 256 dims.
//   PV-phase: same rows, (w>>2) dim-group 128; k = 64 keys.
// ---------------------------------------------------------------------------
#define AQ_LD 264    // halves (528B rows: LDSM conflict-free)
#define AP_LD 72     // halves (144B rows: LDSM conflict-free)
#define APS_LD 67    // floats
#define AKV_HALVES 18432   // max(64*264, 256*72)

#define ATT_SMEM_BYTES ((64*AQ_LD*2 + AKV_HALVES*2 + 64*AP_LD*2) * 2 + (64*APS_LD + 3*64) * 4)

__global__ __launch_bounds__(256, 1) void attn_mma_kernel(
    const bf16* __restrict__ qh, const bf16* __restrict__ ql,
    const bf16* __restrict__ kh, const bf16* __restrict__ kl,
    const bf16* __restrict__ vth, const bf16* __restrict__ vtl,
    bf16* __restrict__ ath, bf16* __restrict__ atl)
{
    extern __shared__ char smraw[];
    bf16* Qh  = (bf16*)smraw;
    bf16* Ql  = Qh  + 64 * AQ_LD;
    bf16* KVh = Ql  + 64 * AQ_LD;
    bf16* KVl = KVh + AKV_HALVES;
    bf16* Ph  = KVl + AKV_HALVES;
    bf16* Pl  = Ph  + 64 * AP_LD;
    float* Ps = (float*)(Pl + 64 * AP_LD);
    float* Ms = Ps + 64 * APS_LD;
    float* Ls = Ms + 64;
    float* Cr = Ls + 64;

    const int qt = (int)gridDim.x - 1 - (int)blockIdx.x;  // heavy tiles first
    const int h  = blockIdx.y;
    const int b  = blockIdx.z;
    const int tid = threadIdx.x;
    const int wid = tid >> 5, lane = tid & 31;
    const int g = lane >> 2, tg = lane & 3;
    const int m8 = lane >> 3, ri = lane & 7;
    const int wm  = (wid & 3) * 16;
    const int wn2 = (wid >> 2) * 32;
    const int wd  = (wid >> 2) * 128;
    const int q0 = qt * 64;
    const float scale = 0.0625f;

    // Q tile [64][256] hi/lo via cp.async
    {
        #pragma unroll
        for (int j = 0; j < 8; j++) {
            const int c = tid + 256 * j;
            const int r = c >> 5, cc = (c & 31) * 8;
            const size_t go = (size_t)(b * S_ + q0 + r) * QKDIM_ + h * HD_ + cc;
            cpasync16(Qh + r * AQ_LD + cc, qh + go);
            cpasync16(Ql + r * AQ_LD + cc, ql + go);
        }
        cpcommit();
    }
    if (tid < 64) { Ms[tid] = -INFINITY; Ls[tid] = 0.f; Cr[tid] = 0.f; }

    float oc[16][4] = {};

    for (int kt = 0; kt <= qt; ++kt) {
        const int k0 = kt * 64;
        __syncthreads();  // prev iter done reading KV (V) and P

        // K tile [64 keys][256 dims] hi/lo -> KV region (stride AQ_LD)
        #pragma unroll
        for (int j = 0; j < 8; j++) {
            const int c = tid + 256 * j;
            const int r = c >> 5, cc = (c & 31) * 8;
            const size_t go = (size_t)(b * S_ + k0 + r) * HD_ + cc;
            cpasync16(KVh + r * AQ_LD + cc, kh + go);
            cpasync16(KVl + r * AQ_LD + cc, kl + go);
        }
        cpcommit();
        cpwait<0>();
        __syncthreads();

        // S = Q @ K^T via 3-MMA split (ldmatrix fragments)
        float sc[4][4] = {};
        #pragma unroll
        for (int kk = 0; kk < 256; kk += 16) {
            uint32_t ah[4], al[4];
            {
                const int ao = (wm + (m8 & 1) * 8 + ri) * AQ_LD + kk + (m8 >> 1) * 8;
                ldsm_x4(ah, Qh + ao);
                ldsm_x4(al, Ql + ao);
            }
            uint32_t bh[2][4], bl[2][4];
            #pragma unroll
            for (int p = 0; p < 2; p++) {
                const int bo = (wn2 + p * 16 + (m8 >> 1) * 8 + ri) * AQ_LD + kk + (m8 & 1) * 8;
                ldsm_x4(bh[p], KVh + bo);
                ldsm_x4(bl[p], KVl + bo);
            }
            #pragma unroll
            for (int p = 0; p < 2; p++)
                #pragma unroll
                for (int sub = 0; sub < 2; sub++) {
                    const int nt = p * 2 + sub;
                    mma16816(sc[nt], ah, bh[p][sub*2], bh[p][sub*2+1]);
                    mma16816(sc[nt], ah, bl[p][sub*2], bl[p][sub*2+1]);
                    mma16816(sc[nt], al, bh[p][sub*2], bh[p][sub*2+1]);
                }
        }

        // Scale + causal mask; store S to Ps
        #pragma unroll
        for (int nt = 0; nt < 4; nt++) {
            const int colL = wn2 + nt * 8 + tg * 2;
            const int col  = k0 + colL;
            const int r0g  = q0 + wm + g;
            const int r1g  = r0g + 8;
            float s0 = sc[nt][0] * scale; if (col     > r0g) s0 = -1e30f;
            float s1 = sc[nt][1] * scale; if (col + 1 > r0g) s1 = -1e30f;
            float s2 = sc[nt][2] * scale; if (col     > r1g) s2 = -1e30f;
            float s3 = sc[nt][3] * scale; if (col + 1 > r1g) s3 = -1e30f;
            const int pr = (wm + g) * APS_LD + colL;
            Ps[pr]                  = s0;
            Ps[pr + 1]              = s1;
            Ps[pr + 8 * APS_LD]     = s2;
            Ps[pr + 8 * APS_LD + 1] = s3;
        }
        __syncthreads();

        // tid<64: online softmax -> Ph/Pl. tid>=64: V tile (dim-major) via cp.async.
        if (tid < 64) {
            const float m_old = Ms[tid];
            float mx = m_old;
            const float* pr = Ps + tid * APS_LD;
            #pragma unroll 8
            for (int j = 0; j < 64; j++) mx = fmaxf(mx, pr[j]);
            const float corr = (m_old == -INFINITY) ? 0.f : __expf(m_old - mx);
            float l = Ls[tid] * corr;
            #pragma unroll 4
            for (int j = 0; j < 64; j++) {
                const float p = __expf(pr[j] - mx);
                bf16 hb, lb; split1(p, hb, lb);
                Ph[tid * AP_LD + j] = hb;
                Pl[tid * AP_LD + j] = lb;
                l += p;
            }
            Ms[tid] = mx; Ls[tid] = l; Cr[tid] = corr;
        } else {
            for (int c = tid - 64; c < 2048; c += 192) {
                const int r = c >> 3, cc = (c & 7) * 8;
                const size_t go = (size_t)b * HD_ * S_ + (size_t)r * S_ + k0 + cc;
                cpasync16(KVh + r * AP_LD + cc, vth + go);
                cpasync16(KVl + r * AP_LD + cc, vtl + go);
            }
            cpcommit();
            cpwait<0>();
        }
        __syncthreads();

        // Rescale accumulator, then O += P @ V (3-MMA split, ldmatrix)
        const float cr0 = Cr[wm + g], cr1 = Cr[wm + g + 8];
        #pragma unroll
        for (int nt = 0; nt < 16; nt++) {
            oc[nt][0] *= cr0; oc[nt][1] *= cr0;
            oc[nt][2] *= cr1; oc[nt][3] *= cr1;
        }
        #pragma unroll
        for (int kk = 0; kk < 64; kk += 16) {
            uint32_t pa[4], pl_[4];
            {
                const int ao = (wm + (m8 & 1) * 8 + ri) * AP_LD + kk + (m8 >> 1) * 8;
                ldsm_x4(pa,  Ph + ao);
                ldsm_x4(pl_, Pl + ao);
            }
            #pragma unroll
            for (int p = 0; p < 8; p++) {
                uint32_t bh[4], bl[4];
                const int bo = (wd + p * 16 + (m8 >> 1) * 8 + ri) * AP_LD + kk + (m8 & 1) * 8;
                ldsm_x4(bh, KVh + bo);
                ldsm_x4(bl, KVl + bo);
                #pragma unroll
                for (int sub = 0; sub < 2; sub++) {
                    const int nt = p * 2 + sub;
                    mma16816(oc[nt], pa,  bh[sub*2], bh[sub*2+1]);
                    mma16816(oc[nt], pa,  bl[sub*2], bl[sub*2+1]);
                    mma16816(oc[nt], pl_, bh[sub*2], bh[sub*2+1]);
                }
            }
        }
    }

    // Epilogue: normalize, split to bf16, write [b,s, h*HD+d]
    const float inv0 = 1.f / Ls[wm + g];
    const float inv1 = 1.f / Ls[wm + g + 8];
    #pragma unroll
    for (int nt = 0; nt < 16; nt++) {
        const int d = wd + nt * 8 + tg * 2;
        const size_t base0 = (size_t)(b * S_ + q0 + wm + g) * QKDIM_ + h * HD_ + d;
        const size_t base1 = base0 + 8 * QKDIM_;
        const float v0 = oc[nt][0] * inv0, v1 = oc[nt][1] * inv0;
        const float v2 = oc[nt][2] * inv1, v3 = oc[nt][3] * inv1;
        bf16 h0,l0,h1,l1,h2,l2,h3,l3;
        split1(v0,h0,l0); split1(v1,h1,l1); split1(v2,h2,l2); split1(v3,h3,l3);
        __nv_bfloat162 t;
        t.x=h0; t.y=h1; *(__nv_bfloat162*)(ath + base0) = t;
        t.x=l0; t.y=l1; *(__nv_bfloat162*)(atl + base0) = t;
        t.x=h2; t.y=h3; *(__nv_bfloat162*)(ath + base1) = t;
        t.x=l2; t.y=l3; *(__nv_bfloat162*)(atl + base1) = t;
    }
}

// ---------------------------------------------------------------------------
// Launch
// Inputs: 0=hidden_states 1=attention_mask(unused) 2=position_ids
//         3=Wq 4=Wk 5=Wv 6=Wo
// ---------------------------------------------------------------------------
extern "C" void kernel_launch(void* const* d_in, const int* in_sizes, int n_in,
                              void* d_out, int out_size) {
    (void)in_sizes; (void)n_in; (void)out_size;
    const float* hs  = (const float*)d_in[0];
    const int*   pos = (const int*)  d_in[2];
    const float* Wq  = (const float*)d_in[3];
    const float* Wk  = (const float*)d_in[4];
    const float* Wv  = (const float*)d_in[5];
    const float* Wo  = (const float*)d_in[6];
    float* out = (float*)d_out;

    float *qkv;
    bf16 *hsh,*hsl,*qh,*ql,*kh,*kl,*vth,*vtl,*ath,*atl;
    bf16 *wallh,*walll,*woh,*wol;
    cudaGetSymbolAddress((void**)&qkv, g_qkv);
    cudaGetSymbolAddress((void**)&hsh, g_hsh); cudaGetSymbolAddress((void**)&hsl, g_hsl);
    cudaGetSymbolAddress((void**)&qh,  g_qh);  cudaGetSymbolAddress((void**)&ql,  g_ql);
    cudaGetSymbolAddress((void**)&kh,  g_kh);  cudaGetSymbolAddress((void**)&kl,  g_kl);
    cudaGetSymbolAddress((void**)&vth, g_vth); cudaGetSymbolAddress((void**)&vtl, g_vtl);
    cudaGetSymbolAddress((void**)&ath, g_ath); cudaGetSymbolAddress((void**)&atl, g_atl);
    cudaGetSymbolAddress((void**)&wallh, g_wallh); cudaGetSymbolAddress((void**)&walll, g_walll);
    cudaGetSymbolAddress((void**)&woh, g_woh); cudaGetSymbolAddress((void**)&wol, g_wol);

    cudaFuncSetAttribute(gemm_bf16s,
        cudaFuncAttributeMaxDynamicSharedMemorySize, GEMM_SMEM);
    cudaFuncSetAttribute(attn_mma_kernel,
        cudaFuncAttributeMaxDynamicSharedMemorySize, ATT_SMEM_BYTES);

    const dim3 tb(32, 8);

    // Split hidden states; transpose+split weights into fused [2560][2048] B
    split_strided_kernel<<<(M_ * HID_ / 4 + 255) / 256, 256>>>(
        hs, hsh, hsl, M_ * HID_, 11, HID_);
    transpose_split_kernel<<<dim3(64, 64, 1), tb>>>(         // Wq -> rows 0..2047
        Wq, wallh, walll, QKDIM_, 0, HID_, 0);
    transpose_split_kernel<<<dim3(8, 64, 1), tb>>>(          // Wk -> rows 2048..2303
        Wk, wallh + (size_t)QKDIM_ * HID_, walll + (size_t)QKDIM_ * HID_,
        HD_, 0, HID_, 0);
    transpose_split_kernel<<<dim3(8, 64, 1), tb>>>(          // Wv -> rows 2304..2559
        Wv, wallh + (size_t)(QKDIM_ + HD_) * HID_, walll + (size_t)(QKDIM_ + HD_) * HID_,
        HD_, 0, HID_, 0);
    transpose_split_kernel<<<dim3(64, 64, 1), tb>>>(         // Wo^T
        Wo, woh, wol, HID_, 0, QKDIM_, 0);

    // Fused QKV projection (tensor core): C[4096][2560]
    gemm_bf16s<<<dim3(NQKV_ / 128, M_ / 128), 256, GEMM_SMEM>>>(
        hsh, hsl, wallh, walll, qkv, M_, NQKV_, HID_);

    // RoPE (fp32, in-place on qkv)
    {
        const int total = B_ * S_ * NH_ * (HD_ / 2) + B_ * S_ * (HD_ / 2);
        rope_kernel<<<(total + 255) / 256, 256>>>(qkv, pos);
    }

    // Split Q/K; transpose+split V per batch
    split_strided_kernel<<<(M_ * QKDIM_ / 4 + 255) / 256, 256>>>(
        qkv, qh, ql, M_ * QKDIM_, 11, NQKV_);
    split_strided_kernel<<<(M_ * HD_ / 4 + 255) / 256, 256>>>(
        qkv + QKDIM_, kh, kl, M_ * HD_, 8, NQKV_);
    transpose_split_kernel<<<dim3(8, 64, B_), tb>>>(
        qkv + QKDIM_ + HD_, vth, vtl,
        NQKV_, (size_t)S_ * NQKV_, S_, (size_t)HD_ * S_);

    // Attention (tensor core flash)
    attn_mma_kernel<<<dim3(S_ / 64, NH_, B_), 256, ATT_SMEM_BYTES>>>(
        qh, ql, kh, kl, vth, vtl, ath, atl);

    // Output projection (tensor core)
    gemm_bf16s<<<dim3(HID_ / 128, M_ / 128), 256, GEMM_SMEM>>>(
        ath, atl, woh, wol, out, M_, HID_, HID_);
}

// round 8
// speedup vs baseline: 2.4615x; 1.0318x over previous
#include <cuda_runtime.h>
#include <cuda_bf16.h>
#include <math.h>
#include <stdint.h>

// Problem constants
#define B_ 2
#define S_ 2048
#define HID_ 2048
#define NH_ 8
#define HD_ 256
#define M_ 4096           // B*S
#define QKDIM_ (NH_*HD_)  // 2048
#define NQKV_ 2560        // 2048 (Q) + 256 (K) + 256 (V)

typedef __nv_bfloat16 bf16;

// ---------------------------------------------------------------------------
// Scratch (device globals: allocation-free per harness rules)
// ---------------------------------------------------------------------------
__device__ float g_qkv[M_ * NQKV_];                         // fused QKV output (fp32)

__device__ bf16 g_hsh[M_ * HID_],  g_hsl[M_ * HID_];        // split hidden_states
__device__ bf16 g_qh [M_ * QKDIM_], g_ql [M_ * QKDIM_];     // split Q (post-RoPE)
__device__ bf16 g_kh [M_ * HD_],   g_kl [M_ * HD_];         // split K
__device__ bf16 g_vth[B_ * HD_ * S_], g_vtl[B_ * HD_ * S_]; // V transposed [b][d][s]
__device__ bf16 g_ath[M_ * QKDIM_], g_atl[M_ * QKDIM_];     // split attention output

__device__ bf16 g_wallh[NQKV_ * HID_];                      // fused [Wq;Wk;Wv]^T hi
__device__ bf16 g_walll[NQKV_ * HID_];                      // fused lo
__device__ bf16 g_woh[QKDIM_ * HID_], g_wol[QKDIM_ * HID_];

// ---------------------------------------------------------------------------
// Helpers
// ---------------------------------------------------------------------------
__device__ __forceinline__ void split1(float x, bf16& h, bf16& l) {
    h = __float2bfloat16(x);
    l = __float2bfloat16(x - __bfloat162float(h));
}

__device__ __forceinline__ void mma16816(float (&d)[4], const uint32_t (&a)[4],
                                         uint32_t b0, uint32_t b1) {
    asm volatile(
        "mma.sync.aligned.m16n8k16.row.col.f32.bf16.bf16.f32 "
        "{%0,%1,%2,%3}, {%4,%5,%6,%7}, {%8,%9}, {%0,%1,%2,%3};\n"
        : "+f"(d[0]), "+f"(d[1]), "+f"(d[2]), "+f"(d[3])
        : "r"(a[0]), "r"(a[1]), "r"(a[2]), "r"(a[3]), "r"(b0), "r"(b1));
}

__device__ __forceinline__ void ldsm_x4(uint32_t (&r)[4], const bf16* p) {
    uint32_t a = (uint32_t)__cvta_generic_to_shared(p);
    asm volatile("ldmatrix.sync.aligned.m8n8.x4.shared.b16 {%0,%1,%2,%3}, [%4];\n"
        : "=r"(r[0]), "=r"(r[1]), "=r"(r[2]), "=r"(r[3]) : "r"(a));
}

__device__ __forceinline__ void cpasync16(bf16* s, const bf16* g) {
    uint32_t sa = (uint32_t)__cvta_generic_to_shared(s);
    asm volatile("cp.async.cg.shared.global [%0], [%1], 16;\n" :: "r"(sa), "l"(g));
}
__device__ __forceinline__ void cpcommit() {
    asm volatile("cp.async.commit_group;\n");
}
template<int N> __device__ __forceinline__ void cpwait() {
    asm volatile("cp.async.wait_group %0;\n" :: "n"(N));
}

// ---------------------------------------------------------------------------
// Elementwise split with strided source.
// ---------------------------------------------------------------------------
__global__ void split_strided_kernel(const float* __restrict__ in,
                                     bf16* __restrict__ oh, bf16* __restrict__ ol,
                                     int n, int colshift, int ldin) {
    int i = (blockIdx.x * blockDim.x + threadIdx.x) * 4;
    if (i >= n) return;
    int r = i >> colshift;
    int c = i & ((1 << colshift) - 1);
    float4 v = *(const float4*)(in + (size_t)r * ldin + c);
    bf16 h0,l0,h1,l1,h2,l2,h3,l3;
    split1(v.x,h0,l0); split1(v.y,h1,l1); split1(v.z,h2,l2); split1(v.w,h3,l3);
    __nv_bfloat162 a, b;
    a.x=h0; a.y=h1; b.x=h2; b.y=h3;
    *(__nv_bfloat162*)(oh+i)   = a; *(__nv_bfloat162*)(oh+i+2) = b;
    a.x=l0; a.y=l1; b.x=l2; b.y=l3;
    *(__nv_bfloat162*)(ol+i)   = a; *(__nv_bfloat162*)(ol+i+2) = b;
}

// ---------------------------------------------------------------------------
// Tiled transpose + split.
// ---------------------------------------------------------------------------
__global__ void transpose_split_kernel(const float* __restrict__ in,
                                       bf16* __restrict__ oh, bf16* __restrict__ ol,
                                       int ldin, size_t bsIn, int ldout, size_t bsOut) {
    __shared__ float t[32][33];
    const float* ip = in + (size_t)blockIdx.z * bsIn;
    bf16* ohp = oh + (size_t)blockIdx.z * bsOut;
    bf16* olp = ol + (size_t)blockIdx.z * bsOut;
    const int r0 = blockIdx.y * 32, c0 = blockIdx.x * 32;
    #pragma unroll
    for (int i = 0; i < 4; i++) {
        int r = threadIdx.y + i * 8;
        t[r][threadIdx.x] = ip[(size_t)(r0 + r) * ldin + c0 + threadIdx.x];
    }
    __syncthreads();
    #pragma unroll
    for (int i = 0; i < 4; i++) {
        int c = threadIdx.y + i * 8;
        float v = t[threadIdx.x][c];
        bf16 h, l; split1(v, h, l);
        size_t o = (size_t)(c0 + c) * ldout + r0 + threadIdx.x;
        ohp[o] = h; olp[o] = l;
    }
}

// ---------------------------------------------------------------------------
// GEMM: C[M,N] = A[M,K] @ B^T, A split bf16 [M][K], B split bf16 [N][K].
// 128x128 tile, BK=32, 256 threads (8 warps 4x2, warp tile 32x64).
// 4-stage cp.async pipeline + ldmatrix fragments + 3-MMA bf16 split.
// ---------------------------------------------------------------------------
#define GLDA 40                    // 32 + 8 halves pad (80B row: LDSM conflict-free)
#define PLANEH (128 * GLDA)        // 5120 halves per plane
#define STAGEH (4 * PLANEH)        // Ah, Al, Bh, Bl
#define GEMM_SMEM (4 * STAGEH * 2) // 4 stages: 163840 bytes

__global__ __launch_bounds__(256) void gemm_bf16s(
    const bf16* __restrict__ Ah, const bf16* __restrict__ Al,
    const bf16* __restrict__ Bh, const bf16* __restrict__ Bl,
    float* __restrict__ C, int M, int N, int K)
{
    extern __shared__ bf16 sm[];
    const int tid = threadIdx.x;
    const int wid = tid >> 5, lane = tid & 31;
    const int g = lane >> 2, tg = lane & 3;
    const int m8 = lane >> 3, ri = lane & 7;     // ldmatrix lane decomposition
    const int wm = (wid & 3) * 32;
    const int wn = (wid >> 2) * 64;
    const int row0 = blockIdx.y * 128;
    const int col0 = blockIdx.x * 128;

    // cp.async mapping: thread -> row tid>>1, halves col (tid&1)*16
    const int lr = tid >> 1;
    const int lc = (tid & 1) * 16;
    const bf16* gA  = Ah + (size_t)(row0 + lr) * K + lc;
    const bf16* gAl = Al + (size_t)(row0 + lr) * K + lc;
    const bf16* gB  = Bh + (size_t)(col0 + lr) * K + lc;
    const bf16* gBl = Bl + (size_t)(col0 + lr) * K + lc;
    const int soff = lr * GLDA + lc;

    float acc[2][8][4] = {};
    const int nk = K / 32;

    auto load_stage = [&](int chunk, int st) {
        const int k0 = chunk * 32;
        bf16* s = sm + st * STAGEH + soff;
        cpasync16(s,            gA  + k0);  cpasync16(s + 8,            gA  + k0 + 8);
        cpasync16(s + PLANEH,   gAl + k0);  cpasync16(s + PLANEH + 8,   gAl + k0 + 8);
        cpasync16(s + 2*PLANEH, gB  + k0);  cpasync16(s + 2*PLANEH + 8, gB  + k0 + 8);
        cpasync16(s + 3*PLANEH, gBl + k0);  cpasync16(s + 3*PLANEH + 8, gBl + k0 + 8);
        cpcommit();
    };

    // prologue: 3 stages in flight
    load_stage(0, 0);
    load_stage(1, 1);
    load_stage(2, 2);

    for (int i = 0; i < nk; i++) {
        // ensure chunk i's group has landed
        if (i <= nk - 3)      cpwait<2>();
        else if (i == nk - 2) cpwait<1>();
        else                  cpwait<0>();
        __syncthreads();   // all warps done reading stage (i+3)&3 (= stage of i-1)

        if (i + 3 < nk) load_stage(i + 3, (i + 3) & 3);

        const bf16* pAh = sm + (i & 3) * STAGEH;
        const bf16* pAl = pAh + PLANEH;
        const bf16* pBh = pAh + 2 * PLANEH;
        const bf16* pBl = pAh + 3 * PLANEH;

        #pragma unroll
        for (int kk = 0; kk < 32; kk += 16) {
            uint32_t ah[2][4], al[2][4];
            #pragma unroll
            for (int mt = 0; mt < 2; mt++) {
                const int ao = (wm + mt * 16 + (m8 & 1) * 8 + ri) * GLDA + kk + (m8 >> 1) * 8;
                ldsm_x4(ah[mt], pAh + ao);
                ldsm_x4(al[mt], pAl + ao);
            }
            uint32_t bh[4][4], bl[4][4];
            #pragma unroll
            for (int p = 0; p < 4; p++) {
                const int bo = (wn + p * 16 + (m8 >> 1) * 8 + ri) * GLDA + kk + (m8 & 1) * 8;
                ldsm_x4(bh[p], pBh + bo);
                ldsm_x4(bl[p], pBl + bo);
            }
            #pragma unroll
            for (int p = 0; p < 4; p++)
                #pragma unroll
                for (int sub = 0; sub < 2; sub++) {
                    const int nt = p * 2 + sub;
                    const uint32_t h0 = bh[p][sub*2], h1 = bh[p][sub*2+1];
                    const uint32_t l0 = bl[p][sub*2], l1 = bl[p][sub*2+1];
                    #pragma unroll
                    for (int mt = 0; mt < 2; mt++) {
                        mma16816(acc[mt][nt], ah[mt], h0, h1);
                        mma16816(acc[mt][nt], ah[mt], l0, l1);
                        mma16816(acc[mt][nt], al[mt], h0, h1);
                    }
                }
        }
    }

    #pragma unroll
    for (int mt = 0; mt < 2; mt++)
        #pragma unroll
        for (int nt = 0; nt < 8; nt++) {
            const int r  = row0 + wm + mt * 16 + g;
            const int cn = col0 + wn + nt * 8 + tg * 2;
            float2 v01; v01.x = acc[mt][nt][0]; v01.y = acc[mt][nt][1];
            float2 v23; v23.x = acc[mt][nt][2]; v23.y = acc[mt][nt][3];
            *(float2*)(C + (size_t)r * N + cn)       = v01;
            *(float2*)(C + (size_t)(r + 8) * N + cn) = v23;
        }
}

// ---------------------------------------------------------------------------
// RoPE in-place on fused QKV buffer [M][2560]: Q at cols h*256, K at col 2048.
// ---------------------------------------------------------------------------
__global__ void rope_kernel(float* __restrict__ qkv, const int* __restrict__ pos)
{
    const int QP = B_ * S_ * NH_ * (HD_ / 2);
    const int KP = B_ * S_ * (HD_ / 2);
    int idx = blockIdx.x * blockDim.x + threadIdx.x;
    if (idx >= QP + KP) return;
    const float L2B = 13.28771237954945f;  // log2(10000)
    int i, bs; float* base;
    if (idx < QP) {
        i  = idx & 127;
        const int h = (idx >> 7) & 7;
        bs = idx >> 10;
        base = qkv + (size_t)bs * NQKV_ + h * HD_;
    } else {
        const int j = idx - QP;
        i  = j & 127;
        bs = j >> 7;
        base = qkv + (size_t)bs * NQKV_ + QKDIM_;
    }
    const float inv = exp2f(-(float)(2 * i) * (L2B / 256.f));
    const float ang = (float)pos[bs] * inv;
    float sn, cs; sincosf(ang, &sn, &cs);
    const float x1 = base[i], x2 = base[i + 128];
    base[i]       = x1 * cs - x2 * sn;
    base[i + 128] = x2 * cs + x1 * sn;
}

// ---------------------------------------------------------------------------
// Flash attention, bf16-split MMAs + ldmatrix + cp.async tile loads.
// CTA = (qtile(64), head, batch), 256 threads = 8 warps.
// Softmax parallelized 2 threads/row (threads 0..127, named barrier) while
// threads 128..255 load the V tile.
// ---------------------------------------------------------------------------
#define AQ_LD 264
#define AP_LD 72
#define APS_LD 67
#define AKV_HALVES 18432

#define ATT_SMEM_BYTES ((64*AQ_LD*2 + AKV_HALVES*2 + 64*AP_LD*2) * 2 \
                        + (64*APS_LD + 3*64 + 256) * 4)

__global__ __launch_bounds__(256, 1) void attn_mma_kernel(
    const bf16* __restrict__ qh, const bf16* __restrict__ ql,
    const bf16* __restrict__ kh, const bf16* __restrict__ kl,
    const bf16* __restrict__ vth, const bf16* __restrict__ vtl,
    bf16* __restrict__ ath, bf16* __restrict__ atl)
{
    extern __shared__ char smraw[];
    bf16* Qh  = (bf16*)smraw;
    bf16* Ql  = Qh  + 64 * AQ_LD;
    bf16* KVh = Ql  + 64 * AQ_LD;
    bf16* KVl = KVh + AKV_HALVES;
    bf16* Ph  = KVl + AKV_HALVES;
    bf16* Pl  = Ph  + 64 * AP_LD;
    float* Ps = (float*)(Pl + 64 * AP_LD);
    float* Ms = Ps + 64 * APS_LD;
    float* Ls = Ms + 64;
    float* Cr = Ls + 64;
    float* Pm  = Cr + 64;    // [128] partial max
    float* Psm = Pm + 128;   // [128] partial sum

    const int qt = (int)gridDim.x - 1 - (int)blockIdx.x;  // heavy tiles first
    const int h  = blockIdx.y;
    const int b  = blockIdx.z;
    const int tid = threadIdx.x;
    const int wid = tid >> 5, lane = tid & 31;
    const int g = lane >> 2, tg = lane & 3;
    const int m8 = lane >> 3, ri = lane & 7;
    const int wm  = (wid & 3) * 16;
    const int wn2 = (wid >> 2) * 32;
    const int wd  = (wid >> 2) * 128;
    const int q0 = qt * 64;
    const float scale = 0.0625f;

    {
        #pragma unroll
        for (int j = 0; j < 8; j++) {
            const int c = tid + 256 * j;
            const int r = c >> 5, cc = (c & 31) * 8;
            const size_t go = (size_t)(b * S_ + q0 + r) * QKDIM_ + h * HD_ + cc;
            cpasync16(Qh + r * AQ_LD + cc, qh + go);
            cpasync16(Ql + r * AQ_LD + cc, ql + go);
        }
        cpcommit();
    }
    if (tid < 64) { Ms[tid] = -INFINITY; Ls[tid] = 0.f; Cr[tid] = 0.f; }

    float oc[16][4] = {};

    for (int kt = 0; kt <= qt; ++kt) {
        const int k0 = kt * 64;
        __syncthreads();

        #pragma unroll
        for (int j = 0; j < 8; j++) {
            const int c = tid + 256 * j;
            const int r = c >> 5, cc = (c & 31) * 8;
            const size_t go = (size_t)(b * S_ + k0 + r) * HD_ + cc;
            cpasync16(KVh + r * AQ_LD + cc, kh + go);
            cpasync16(KVl + r * AQ_LD + cc, kl + go);
        }
        cpcommit();
        cpwait<0>();
        __syncthreads();

        float sc[4][4] = {};
        #pragma unroll
        for (int kk = 0; kk < 256; kk += 16) {
            uint32_t ah[4], al[4];
            {
                const int ao = (wm + (m8 & 1) * 8 + ri) * AQ_LD + kk + (m8 >> 1) * 8;
                ldsm_x4(ah, Qh + ao);
                ldsm_x4(al, Ql + ao);
            }
            uint32_t bh[2][4], bl[2][4];
            #pragma unroll
            for (int p = 0; p < 2; p++) {
                const int bo = (wn2 + p * 16 + (m8 >> 1) * 8 + ri) * AQ_LD + kk + (m8 & 1) * 8;
                ldsm_x4(bh[p], KVh + bo);
                ldsm_x4(bl[p], KVl + bo);
            }
            #pragma unroll
            for (int p = 0; p < 2; p++)
                #pragma unroll
                for (int sub = 0; sub < 2; sub++) {
                    const int nt = p * 2 + sub;
                    mma16816(sc[nt], ah, bh[p][sub*2], bh[p][sub*2+1]);
                    mma16816(sc[nt], ah, bl[p][sub*2], bl[p][sub*2+1]);
                    mma16816(sc[nt], al, bh[p][sub*2], bh[p][sub*2+1]);
                }
        }

        #pragma unroll
        for (int nt = 0; nt < 4; nt++) {
            const int colL = wn2 + nt * 8 + tg * 2;
            const int col  = k0 + colL;
            const int r0g  = q0 + wm + g;
            const int r1g  = r0g + 8;
            float s0 = sc[nt][0] * scale; if (col     > r0g) s0 = -1e30f;
            float s1 = sc[nt][1] * scale; if (col + 1 > r0g) s1 = -1e30f;
            float s2 = sc[nt][2] * scale; if (col     > r1g) s2 = -1e30f;
            float s3 = sc[nt][3] * scale; if (col + 1 > r1g) s3 = -1e30f;
            const int pr = (wm + g) * APS_LD + colL;
            Ps[pr]                  = s0;
            Ps[pr + 1]              = s1;
            Ps[pr + 8 * APS_LD]     = s2;
            Ps[pr + 8 * APS_LD + 1] = s3;
        }
        __syncthreads();

        // threads 0..127: softmax, 2 per row. threads 128..255: V tile load.
        if (tid < 128) {
            const int row  = tid & 63;
            const int half = tid >> 6;
            const float* pr = Ps + row * APS_LD + half * 32;
            float mx = -INFINITY;
            #pragma unroll 8
            for (int j = 0; j < 32; j++) mx = fmaxf(mx, pr[j]);
            Pm[tid] = mx;
            asm volatile("bar.sync 1, 128;" ::: "memory");
            const float m_old = Ms[row];
            const float mnew = fmaxf(fmaxf(Pm[row], Pm[row + 64]), m_old);
            float s = 0.f;
            bf16* php = Ph + row * AP_LD + half * 32;
            bf16* plp = Pl + row * AP_LD + half * 32;
            #pragma unroll 4
            for (int j = 0; j < 32; j++) {
                const float p = __expf(pr[j] - mnew);
                bf16 hb, lb; split1(p, hb, lb);
                php[j] = hb; plp[j] = lb;
                s += p;
            }
            Psm[tid] = s;
            asm volatile("bar.sync 1, 128;" ::: "memory");
            if (half == 0) {
                const float corr = (m_old == -INFINITY) ? 0.f : __expf(m_old - mnew);
                Ls[row] = Ls[row] * corr + Psm[row] + Psm[row + 64];
                Ms[row] = mnew;
                Cr[row] = corr;
            }
        } else {
            for (int c = tid - 128; c < 2048; c += 128) {
                const int r = c >> 3, cc = (c & 7) * 8;
                const size_t go = (size_t)b * HD_ * S_ + (size_t)r * S_ + k0 + cc;
                cpasync16(KVh + r * AP_LD + cc, vth + go);
                cpasync16(KVl + r * AP_LD + cc, vtl + go);
            }
            cpcommit();
            cpwait<0>();
        }
        __syncthreads();

        const float cr0 = Cr[wm + g], cr1 = Cr[wm + g + 8];
        #pragma unroll
        for (int nt = 0; nt < 16; nt++) {
            oc[nt][0] *= cr0; oc[nt][1] *= cr0;
            oc[nt][2] *= cr1; oc[nt][3] *= cr1;
        }
        #pragma unroll
        for (int kk = 0; kk < 64; kk += 16) {
            uint32_t pa[4], pl_[4];
            {
                const int ao = (wm + (m8 & 1) * 8 + ri) * AP_LD + kk + (m8 >> 1) * 8;
                ldsm_x4(pa,  Ph + ao);
                ldsm_x4(pl_, Pl + ao);
            }
            #pragma unroll
            for (int p = 0; p < 8; p++) {
                uint32_t bh[4], bl[4];
                const int bo = (wd + p * 16 + (m8 >> 1) * 8 + ri) * AP_LD + kk + (m8 & 1) * 8;
                ldsm_x4(bh, KVh + bo);
                ldsm_x4(bl, KVl + bo);
                #pragma unroll
                for (int sub = 0; sub < 2; sub++) {
                    const int nt = p * 2 + sub;
                    mma16816(oc[nt], pa,  bh[sub*2], bh[sub*2+1]);
                    mma16816(oc[nt], pa,  bl[sub*2], bl[sub*2+1]);
                    mma16816(oc[nt], pl_, bh[sub*2], bh[sub*2+1]);
                }
            }
        }
    }

    const float inv0 = 1.f / Ls[wm + g];
    const float inv1 = 1.f / Ls[wm + g + 8];
    #pragma unroll
    for (int nt = 0; nt < 16; nt++) {
        const int d = wd + nt * 8 + tg * 2;
        const size_t base0 = (size_t)(b * S_ + q0 + wm + g) * QKDIM_ + h * HD_ + d;
        const size_t base1 = base0 + 8 * QKDIM_;
        const float v0 = oc[nt][0] * inv0, v1 = oc[nt][1] * inv0;
        const float v2 = oc[nt][2] * inv1, v3 = oc[nt][3] * inv1;
        bf16 h0,l0,h1,l1,h2,l2,h3,l3;
        split1(v0,h0,l0); split1(v1,h1,l1); split1(v2,h2,l2); split1(v3,h3,l3);
        __nv_bfloat162 t;
        t.x=h0; t.y=h1; *(__nv_bfloat162*)(ath + base0) = t;
        t.x=l0; t.y=l1; *(__nv_bfloat162*)(atl + base0) = t;
        t.x=h2; t.y=h3; *(__nv_bfloat162*)(ath + base1) = t;
        t.x=l2; t.y=l3; *(__nv_bfloat162*)(atl + base1) = t;
    }
}

// ---------------------------------------------------------------------------
// Launch
// Inputs: 0=hidden_states 1=attention_mask(unused) 2=position_ids
//         3=Wq 4=Wk 5=Wv 6=Wo
// ---------------------------------------------------------------------------
extern "C" void kernel_launch(void* const* d_in, const int* in_sizes, int n_in,
                              void* d_out, int out_size) {
    (void)in_sizes; (void)n_in; (void)out_size;
    const float* hs  = (const float*)d_in[0];
    const int*   pos = (const int*)  d_in[2];
    const float* Wq  = (const float*)d_in[3];
    const float* Wk  = (const float*)d_in[4];
    const float* Wv  = (const float*)d_in[5];
    const float* Wo  = (const float*)d_in[6];
    float* out = (float*)d_out;

    float *qkv;
    bf16 *hsh,*hsl,*qh,*ql,*kh,*kl,*vth,*vtl,*ath,*atl;
    bf16 *wallh,*walll,*woh,*wol;
    cudaGetSymbolAddress((void**)&qkv, g_qkv);
    cudaGetSymbolAddress((void**)&hsh, g_hsh); cudaGetSymbolAddress((void**)&hsl, g_hsl);
    cudaGetSymbolAddress((void**)&qh,  g_qh);  cudaGetSymbolAddress((void**)&ql,  g_ql);
    cudaGetSymbolAddress((void**)&kh,  g_kh);  cudaGetSymbolAddress((void**)&kl,  g_kl);
    cudaGetSymbolAddress((void**)&vth, g_vth); cudaGetSymbolAddress((void**)&vtl, g_vtl);
    cudaGetSymbolAddress((void**)&ath, g_ath); cudaGetSymbolAddress((void**)&atl, g_atl);
    cudaGetSymbolAddress((void**)&wallh, g_wallh); cudaGetSymbolAddress((void**)&walll, g_walll);
    cudaGetSymbolAddress((void**)&woh, g_woh); cudaGetSymbolAddress((void**)&wol, g_wol);

    cudaFuncSetAttribute(gemm_bf16s,
        cudaFuncAttributeMaxDynamicSharedMemorySize, GEMM_SMEM);
    cudaFuncSetAttribute(attn_mma_kernel,
        cudaFuncAttributeMaxDynamicSharedMemorySize, ATT_SMEM_BYTES);

    const dim3 tb(32, 8);

    // Split hidden states; transpose+split weights into fused [2560][2048] B
    split_strided_kernel<<<(M_ * HID_ / 4 + 255) / 256, 256>>>(
        hs, hsh, hsl, M_ * HID_, 11, HID_);
    transpose_split_kernel<<<dim3(64, 64, 1), tb>>>(
        Wq, wallh, walll, QKDIM_, 0, HID_, 0);
    transpose_split_kernel<<<dim3(8, 64, 1), tb>>>(
        Wk, wallh + (size_t)QKDIM_ * HID_, walll + (size_t)QKDIM_ * HID_,
        HD_, 0, HID_, 0);
    transpose_split_kernel<<<dim3(8, 64, 1), tb>>>(
        Wv, wallh + (size_t)(QKDIM_ + HD_) * HID_, walll + (size_t)(QKDIM_ + HD_) * HID_,
        HD_, 0, HID_, 0);
    transpose_split_kernel<<<dim3(64, 64, 1), tb>>>(
        Wo, woh, wol, HID_, 0, QKDIM_, 0);

    // Fused QKV projection (tensor core): C[4096][2560]
    gemm_bf16s<<<dim3(NQKV_ / 128, M_ / 128), 256, GEMM_SMEM>>>(
        hsh, hsl, wallh, walll, qkv, M_, NQKV_, HID_);

    // RoPE (fp32, in-place on qkv)
    {
        const int total = B_ * S_ * NH_ * (HD_ / 2) + B_ * S_ * (HD_ / 2);
        rope_kernel<<<(total + 255) / 256, 256>>>(qkv, pos);
    }

    // Split Q/K; transpose+split V per batch
    split_strided_kernel<<<(M_ * QKDIM_ / 4 + 255) / 256, 256>>>(
        qkv, qh, ql, M_ * QKDIM_, 11, NQKV_);
    split_strided_kernel<<<(M_ * HD_ / 4 + 255) / 256, 256>>>(
        qkv + QKDIM_, kh, kl, M_ * HD_, 8, NQKV_);
    transpose_split_kernel<<<dim3(8, 64, B_), tb>>>(
        qkv + QKDIM_ + HD_, vth, vtl,
        NQKV_, (size_t)S_ * NQKV_, S_, (size_t)HD_ * S_);

    // Attention (tensor core flash)
    attn_mma_kernel<<<dim3(S_ / 64, NH_, B_), 256, ATT_SMEM_BYTES>>>(
        qh, ql, kh, kl, vth, vtl, ath, atl);

    // Output projection (tensor core)
    gemm_bf16s<<<dim3(HID_ / 128, M_ / 128), 256, GEMM_SMEM>>>(
        ath, atl, woh, wol, out, M_, HID_, HID_);
}

// round 9
// speedup vs baseline: 2.6959x; 1.0952x over previous
#include <cuda_runtime.h>
#include <cuda_bf16.h>
#include <math.h>
#include <stdint.h>

// Problem constants
#define B_ 2
#define S_ 2048
#define HID_ 2048
#define NH_ 8
#define HD_ 256
#define M_ 4096           // B*S
#define QKDIM_ (NH_*HD_)  // 2048
#define NQKV_ 2560        // 2048 (Q) + 256 (K) + 256 (V)

typedef __nv_bfloat16 bf16;

// ---------------------------------------------------------------------------
// Scratch (device globals: allocation-free per harness rules)
// ---------------------------------------------------------------------------
__device__ float g_qkv[M_ * NQKV_];                         // fused QKV output (fp32)

__device__ bf16 g_hsh[M_ * HID_],  g_hsl[M_ * HID_];        // split hidden_states
__device__ bf16 g_qh [M_ * QKDIM_], g_ql [M_ * QKDIM_];     // split Q (post-RoPE)
__device__ bf16 g_kh [M_ * HD_],   g_kl [M_ * HD_];         // split K
__device__ bf16 g_vth[B_ * HD_ * S_], g_vtl[B_ * HD_ * S_]; // V transposed [b][d][s]
__device__ bf16 g_ath[M_ * QKDIM_], g_atl[M_ * QKDIM_];     // split attention output

__device__ bf16 g_wallh[NQKV_ * HID_];                      // fused [Wq;Wk;Wv]^T hi
__device__ bf16 g_walll[NQKV_ * HID_];                      // fused lo
__device__ bf16 g_woh[QKDIM_ * HID_], g_wol[QKDIM_ * HID_];

// ---------------------------------------------------------------------------
// Helpers
// ---------------------------------------------------------------------------
__device__ __forceinline__ void split1(float x, bf16& h, bf16& l) {
    h = __float2bfloat16(x);
    l = __float2bfloat16(x - __bfloat162float(h));
}

__device__ __forceinline__ void mma16816(float (&d)[4], const uint32_t (&a)[4],
                                         uint32_t b0, uint32_t b1) {
    asm volatile(
        "mma.sync.aligned.m16n8k16.row.col.f32.bf16.bf16.f32 "
        "{%0,%1,%2,%3}, {%4,%5,%6,%7}, {%8,%9}, {%0,%1,%2,%3};\n"
        : "+f"(d[0]), "+f"(d[1]), "+f"(d[2]), "+f"(d[3])
        : "r"(a[0]), "r"(a[1]), "r"(a[2]), "r"(a[3]), "r"(b0), "r"(b1));
}

__device__ __forceinline__ void ldsm_x4(uint32_t (&r)[4], const bf16* p) {
    uint32_t a = (uint32_t)__cvta_generic_to_shared(p);
    asm volatile("ldmatrix.sync.aligned.m8n8.x4.shared.b16 {%0,%1,%2,%3}, [%4];\n"
        : "=r"(r[0]), "=r"(r[1]), "=r"(r[2]), "=r"(r[3]) : "r"(a));
}

__device__ __forceinline__ void cpasync16(bf16* s, const bf16* g) {
    uint32_t sa = (uint32_t)__cvta_generic_to_shared(s);
    asm volatile("cp.async.cg.shared.global [%0], [%1], 16;\n" :: "r"(sa), "l"(g));
}
__device__ __forceinline__ void cpcommit() {
    asm volatile("cp.async.commit_group;\n");
}
template<int N> __device__ __forceinline__ void cpwait() {
    asm volatile("cp.async.wait_group %0;\n" :: "n"(N));
}

// ---------------------------------------------------------------------------
// Elementwise split with strided source.
// ---------------------------------------------------------------------------
__global__ void split_strided_kernel(const float* __restrict__ in,
                                     bf16* __restrict__ oh, bf16* __restrict__ ol,
                                     int n, int colshift, int ldin) {
    int i = (blockIdx.x * blockDim.x + threadIdx.x) * 4;
    if (i >= n) return;
    int r = i >> colshift;
    int c = i & ((1 << colshift) - 1);
    float4 v = *(const float4*)(in + (size_t)r * ldin + c);
    bf16 h0,l0,h1,l1,h2,l2,h3,l3;
    split1(v.x,h0,l0); split1(v.y,h1,l1); split1(v.z,h2,l2); split1(v.w,h3,l3);
    __nv_bfloat162 a, b;
    a.x=h0; a.y=h1; b.x=h2; b.y=h3;
    *(__nv_bfloat162*)(oh+i)   = a; *(__nv_bfloat162*)(oh+i+2) = b;
    a.x=l0; a.y=l1; b.x=l2; b.y=l3;
    *(__nv_bfloat162*)(ol+i)   = a; *(__nv_bfloat162*)(ol+i+2) = b;
}

// ---------------------------------------------------------------------------
// Tiled transpose + split.
// ---------------------------------------------------------------------------
__global__ void transpose_split_kernel(const float* __restrict__ in,
                                       bf16* __restrict__ oh, bf16* __restrict__ ol,
                                       int ldin, size_t bsIn, int ldout, size_t bsOut) {
    __shared__ float t[32][33];
    const float* ip = in + (size_t)blockIdx.z * bsIn;
    bf16* ohp = oh + (size_t)blockIdx.z * bsOut;
    bf16* olp = ol + (size_t)blockIdx.z * bsOut;
    const int r0 = blockIdx.y * 32, c0 = blockIdx.x * 32;
    #pragma unroll
    for (int i = 0; i < 4; i++) {
        int r = threadIdx.y + i * 8;
        t[r][threadIdx.x] = ip[(size_t)(r0 + r) * ldin + c0 + threadIdx.x];
    }
    __syncthreads();
    #pragma unroll
    for (int i = 0; i < 4; i++) {
        int c = threadIdx.y + i * 8;
        float v = t[threadIdx.x][c];
        bf16 h, l; split1(v, h, l);
        size_t o = (size_t)(c0 + c) * ldout + r0 + threadIdx.x;
        ohp[o] = h; olp[o] = l;
    }
}

// ---------------------------------------------------------------------------
// GEMM: C[M,N] = A[M,K] @ B^T, A split bf16 [M][K], B split bf16 [N][K].
// 128x128 tile, BK=32, 256 threads (8 warps 4x2, warp tile 32x64).
// 4-stage cp.async pipeline + ldmatrix fragments + 3-MMA bf16 split.
// ---------------------------------------------------------------------------
#define GLDA 40                    // 32 + 8 halves pad (80B row: LDSM conflict-free)
#define PLANEH (128 * GLDA)        // 5120 halves per plane
#define STAGEH (4 * PLANEH)        // Ah, Al, Bh, Bl
#define GEMM_SMEM (4 * STAGEH * 2) // 4 stages: 163840 bytes

__global__ __launch_bounds__(256) void gemm_bf16s(
    const bf16* __restrict__ Ah, const bf16* __restrict__ Al,
    const bf16* __restrict__ Bh, const bf16* __restrict__ Bl,
    float* __restrict__ C, int M, int N, int K)
{
    extern __shared__ bf16 sm[];
    const int tid = threadIdx.x;
    const int wid = tid >> 5, lane = tid & 31;
    const int g = lane >> 2, tg = lane & 3;
    const int m8 = lane >> 3, ri = lane & 7;     // ldmatrix lane decomposition
    const int wm = (wid & 3) * 32;
    const int wn = (wid >> 2) * 64;
    const int row0 = blockIdx.y * 128;
    const int col0 = blockIdx.x * 128;

    // cp.async mapping: thread -> row tid>>1, halves col (tid&1)*16
    const int lr = tid >> 1;
    const int lc = (tid & 1) * 16;
    const bf16* gA  = Ah + (size_t)(row0 + lr) * K + lc;
    const bf16* gAl = Al + (size_t)(row0 + lr) * K + lc;
    const bf16* gB  = Bh + (size_t)(col0 + lr) * K + lc;
    const bf16* gBl = Bl + (size_t)(col0 + lr) * K + lc;
    const int soff = lr * GLDA + lc;

    float acc[2][8][4] = {};
    const int nk = K / 32;

    auto load_stage = [&](int chunk, int st) {
        const int k0 = chunk * 32;
        bf16* s = sm + st * STAGEH + soff;
        cpasync16(s,            gA  + k0);  cpasync16(s + 8,            gA  + k0 + 8);
        cpasync16(s + PLANEH,   gAl + k0);  cpasync16(s + PLANEH + 8,   gAl + k0 + 8);
        cpasync16(s + 2*PLANEH, gB  + k0);  cpasync16(s + 2*PLANEH + 8, gB  + k0 + 8);
        cpasync16(s + 3*PLANEH, gBl + k0);  cpasync16(s + 3*PLANEH + 8, gBl + k0 + 8);
        cpcommit();
    };

    // prologue: 3 stages in flight
    load_stage(0, 0);
    load_stage(1, 1);
    load_stage(2, 2);

    for (int i = 0; i < nk; i++) {
        if (i <= nk - 3)      cpwait<2>();
        else if (i == nk - 2) cpwait<1>();
        else                  cpwait<0>();
        __syncthreads();

        if (i + 3 < nk) load_stage(i + 3, (i + 3) & 3);

        const bf16* pAh = sm + (i & 3) * STAGEH;
        const bf16* pAl = pAh + PLANEH;
        const bf16* pBh = pAh + 2 * PLANEH;
        const bf16* pBl = pAh + 3 * PLANEH;

        #pragma unroll
        for (int kk = 0; kk < 32; kk += 16) {
            uint32_t ah[2][4], al[2][4];
            #pragma unroll
            for (int mt = 0; mt < 2; mt++) {
                const int ao = (wm + mt * 16 + (m8 & 1) * 8 + ri) * GLDA + kk + (m8 >> 1) * 8;
                ldsm_x4(ah[mt], pAh + ao);
                ldsm_x4(al[mt], pAl + ao);
            }
            uint32_t bh[4][4], bl[4][4];
            #pragma unroll
            for (int p = 0; p < 4; p++) {
                const int bo = (wn + p * 16 + (m8 >> 1) * 8 + ri) * GLDA + kk + (m8 & 1) * 8;
                ldsm_x4(bh[p], pBh + bo);
                ldsm_x4(bl[p], pBl + bo);
            }
            #pragma unroll
            for (int p = 0; p < 4; p++)
                #pragma unroll
                for (int sub = 0; sub < 2; sub++) {
                    const int nt = p * 2 + sub;
                    const uint32_t h0 = bh[p][sub*2], h1 = bh[p][sub*2+1];
                    const uint32_t l0 = bl[p][sub*2], l1 = bl[p][sub*2+1];
                    #pragma unroll
                    for (int mt = 0; mt < 2; mt++) {
                        mma16816(acc[mt][nt], ah[mt], h0, h1);
                        mma16816(acc[mt][nt], ah[mt], l0, l1);
                        mma16816(acc[mt][nt], al[mt], h0, h1);
                    }
                }
        }
    }

    #pragma unroll
    for (int mt = 0; mt < 2; mt++)
        #pragma unroll
        for (int nt = 0; nt < 8; nt++) {
            const int r  = row0 + wm + mt * 16 + g;
            const int cn = col0 + wn + nt * 8 + tg * 2;
            float2 v01; v01.x = acc[mt][nt][0]; v01.y = acc[mt][nt][1];
            float2 v23; v23.x = acc[mt][nt][2]; v23.y = acc[mt][nt][3];
            *(float2*)(C + (size_t)r * N + cn)       = v01;
            *(float2*)(C + (size_t)(r + 8) * N + cn) = v23;
        }
}

// ---------------------------------------------------------------------------
// Fused RoPE + split: reads fp32 pairs from qkv, rotates, writes split bf16
// directly into qh/ql (Q) and kh/kl (K). qkv itself is left untouched.
// ---------------------------------------------------------------------------
__global__ void rope_split_kernel(const float* __restrict__ qkv,
                                  const int* __restrict__ pos,
                                  bf16* __restrict__ qh, bf16* __restrict__ ql,
                                  bf16* __restrict__ kh, bf16* __restrict__ kl)
{
    const int QP = B_ * S_ * NH_ * (HD_ / 2);
    const int KP = B_ * S_ * (HD_ / 2);
    int idx = blockIdx.x * blockDim.x + threadIdx.x;
    if (idx >= QP + KP) return;
    const float L2B = 13.28771237954945f;  // log2(10000)

    int i, bs;
    const float* base;
    bf16 *oh, *ol;
    size_t oo;
    if (idx < QP) {
        i  = idx & 127;
        const int h = (idx >> 7) & 7;
        bs = idx >> 10;
        base = qkv + (size_t)bs * NQKV_ + h * HD_;
        oo = (size_t)bs * QKDIM_ + h * HD_;
        oh = qh; ol = ql;
    } else {
        const int j = idx - QP;
        i  = j & 127;
        bs = j >> 7;
        base = qkv + (size_t)bs * NQKV_ + QKDIM_;
        oo = (size_t)bs * HD_;
        oh = kh; ol = kl;
    }
    const float inv = exp2f(-(float)(2 * i) * (L2B / 256.f));
    const float ang = (float)pos[bs] * inv;
    float sn, cs; sincosf(ang, &sn, &cs);
    const float x1 = base[i], x2 = base[i + 128];
    const float o1 = x1 * cs - x2 * sn;
    const float o2 = x2 * cs + x1 * sn;
    bf16 h1, l1, h2, l2;
    split1(o1, h1, l1); split1(o2, h2, l2);
    oh[oo + i]       = h1;  ol[oo + i]       = l1;
    oh[oo + i + 128] = h2;  ol[oo + i + 128] = l2;
}

// ---------------------------------------------------------------------------
// Flash attention, bf16-split MMAs + ldmatrix + cp.async tile loads.
// CTA = (qtile(64), head, batch), 256 threads = 8 warps.
// In-register softmax: shfl row-max/sum over tg lanes + pair-warp SMEM
// exchange (named barriers). V cp.async issued by all threads before exp.
// ---------------------------------------------------------------------------
#define AQ_LD 264
#define AP_LD 72
#define AKV_HALVES 18432

#define ATT_SMEM_BYTES ((64*AQ_LD*2 + AKV_HALVES*2 + 64*AP_LD*2) * 2 + (3*64 + 256) * 4)

__global__ __launch_bounds__(256, 1) void attn_mma_kernel(
    const bf16* __restrict__ qh, const bf16* __restrict__ ql,
    const bf16* __restrict__ kh, const bf16* __restrict__ kl,
    const bf16* __restrict__ vth, const bf16* __restrict__ vtl,
    bf16* __restrict__ ath, bf16* __restrict__ atl)
{
    extern __shared__ char smraw[];
    bf16* Qh  = (bf16*)smraw;
    bf16* Ql  = Qh  + 64 * AQ_LD;
    bf16* KVh = Ql  + 64 * AQ_LD;
    bf16* KVl = KVh + AKV_HALVES;
    bf16* Ph  = KVl + AKV_HALVES;
    bf16* Pl  = Ph  + 64 * AP_LD;
    float* Ms = (float*)(Pl + 64 * AP_LD);
    float* Ls = Ms + 64;
    float* Cr = Ls + 64;
    float* Mx = Cr + 64;    // [128] pair-warp max exchange
    float* Sx = Mx + 128;   // [128] pair-warp sum exchange

    const int qt = (int)gridDim.x - 1 - (int)blockIdx.x;  // heavy tiles first
    const int h  = blockIdx.y;
    const int b  = blockIdx.z;
    const int tid = threadIdx.x;
    const int wid = tid >> 5, lane = tid & 31;
    const int g = lane >> 2, tg = lane & 3;
    const int m8 = lane >> 3, ri = lane & 7;
    const int wm  = (wid & 3) * 16;
    const int wn2 = (wid >> 2) * 32;
    const int wd  = (wid >> 2) * 128;
    const int half = wid >> 2;
    const int barid = (wid & 3) + 1;
    const int q0 = qt * 64;
    const float scale = 0.0625f;

    {
        #pragma unroll
        for (int j = 0; j < 8; j++) {
            const int c = tid + 256 * j;
            const int r = c >> 5, cc = (c & 31) * 8;
            const size_t go = (size_t)(b * S_ + q0 + r) * QKDIM_ + h * HD_ + cc;
            cpasync16(Qh + r * AQ_LD + cc, qh + go);
            cpasync16(Ql + r * AQ_LD + cc, ql + go);
        }
        cpcommit();
    }
    if (tid < 64) { Ms[tid] = -INFINITY; Ls[tid] = 0.f; Cr[tid] = 0.f; }

    float oc[16][4] = {};

    for (int kt = 0; kt <= qt; ++kt) {
        const int k0 = kt * 64;
        __syncthreads();   // A: prev PV done reading KV (V) and Ph/Pl

        // K tile [64 keys][256 dims] hi/lo -> KV region (stride AQ_LD)
        #pragma unroll
        for (int j = 0; j < 8; j++) {
            const int c = tid + 256 * j;
            const int r = c >> 5, cc = (c & 31) * 8;
            const size_t go = (size_t)(b * S_ + k0 + r) * HD_ + cc;
            cpasync16(KVh + r * AQ_LD + cc, kh + go);
            cpasync16(KVl + r * AQ_LD + cc, kl + go);
        }
        cpcommit();
        cpwait<0>();
        __syncthreads();   // B

        // S = Q @ K^T via 3-MMA split (ldmatrix fragments)
        float sc[4][4] = {};
        #pragma unroll
        for (int kk = 0; kk < 256; kk += 16) {
            uint32_t ah[4], al[4];
            {
                const int ao = (wm + (m8 & 1) * 8 + ri) * AQ_LD + kk + (m8 >> 1) * 8;
                ldsm_x4(ah, Qh + ao);
                ldsm_x4(al, Ql + ao);
            }
            uint32_t bh[2][4], bl[2][4];
            #pragma unroll
            for (int p = 0; p < 2; p++) {
                const int bo = (wn2 + p * 16 + (m8 >> 1) * 8 + ri) * AQ_LD + kk + (m8 & 1) * 8;
                ldsm_x4(bh[p], KVh + bo);
                ldsm_x4(bl[p], KVl + bo);
            }
            #pragma unroll
            for (int p = 0; p < 2; p++)
                #pragma unroll
                for (int sub = 0; sub < 2; sub++) {
                    const int nt = p * 2 + sub;
                    mma16816(sc[nt], ah, bh[p][sub*2], bh[p][sub*2+1]);
                    mma16816(sc[nt], ah, bl[p][sub*2], bl[p][sub*2+1]);
                    mma16816(sc[nt], al, bh[p][sub*2], bh[p][sub*2+1]);
                }
        }

        // scale + causal mask in registers
        const int r0g = q0 + wm + g;
        const int r1g = r0g + 8;
        #pragma unroll
        for (int nt = 0; nt < 4; nt++) {
            const int col = k0 + wn2 + nt * 8 + tg * 2;
            sc[nt][0] = (col     > r0g) ? -1e30f : sc[nt][0] * scale;
            sc[nt][1] = (col + 1 > r0g) ? -1e30f : sc[nt][1] * scale;
            sc[nt][2] = (col     > r1g) ? -1e30f : sc[nt][2] * scale;
            sc[nt][3] = (col + 1 > r1g) ? -1e30f : sc[nt][3] * scale;
        }

        __syncthreads();   // C: all warps done reading K from KV region

        // V tile (dim-major [256][64]) via cp.async, ALL threads (async)
        #pragma unroll
        for (int j = 0; j < 8; j++) {
            const int c = tid + 256 * j;
            const int r = c >> 3, cc = (c & 7) * 8;
            const size_t go = (size_t)b * HD_ * S_ + (size_t)r * S_ + k0 + cc;
            cpasync16(KVh + r * AP_LD + cc, vth + go);
            cpasync16(KVl + r * AP_LD + cc, vtl + go);
        }
        cpcommit();

        // In-register softmax. Rows r0=wm+g, r1=r0+8; 8 cols/row per thread.
        const int lr0 = wm + g, lr1 = lr0 + 8;
        float mx0 = -INFINITY, mx1 = -INFINITY;
        #pragma unroll
        for (int nt = 0; nt < 4; nt++) {
            mx0 = fmaxf(mx0, fmaxf(sc[nt][0], sc[nt][1]));
            mx1 = fmaxf(mx1, fmaxf(sc[nt][2], sc[nt][3]));
        }
        mx0 = fmaxf(mx0, __shfl_xor_sync(0xffffffffu, mx0, 1));
        mx0 = fmaxf(mx0, __shfl_xor_sync(0xffffffffu, mx0, 2));
        mx1 = fmaxf(mx1, __shfl_xor_sync(0xffffffffu, mx1, 1));
        mx1 = fmaxf(mx1, __shfl_xor_sync(0xffffffffu, mx1, 2));
        if (tg == 0) { Mx[half * 64 + lr0] = mx0; Mx[half * 64 + lr1] = mx1; }
        asm volatile("bar.sync %0, 64;" :: "r"(barid) : "memory");   // D (pair)

        const float mo0 = Ms[lr0], mo1 = Ms[lr1];
        const float mn0 = fmaxf(fmaxf(Mx[lr0], Mx[64 + lr0]), mo0);
        const float mn1 = fmaxf(fmaxf(Mx[lr1], Mx[64 + lr1]), mo1);
        float sum0 = 0.f, sum1 = 0.f;
        #pragma unroll
        for (int nt = 0; nt < 4; nt++) {
            const int colL = wn2 + nt * 8 + tg * 2;
            const float p0 = __expf(sc[nt][0] - mn0);
            const float p1 = __expf(sc[nt][1] - mn0);
            const float p2 = __expf(sc[nt][2] - mn1);
            const float p3 = __expf(sc[nt][3] - mn1);
            sum0 += p0 + p1; sum1 += p2 + p3;
            bf16 hb0,lb0,hb1,lb1,hb2,lb2,hb3,lb3;
            split1(p0,hb0,lb0); split1(p1,hb1,lb1);
            split1(p2,hb2,lb2); split1(p3,hb3,lb3);
            __nv_bfloat162 t;
            t.x=hb0; t.y=hb1; *(__nv_bfloat162*)(Ph + lr0 * AP_LD + colL) = t;
            t.x=lb0; t.y=lb1; *(__nv_bfloat162*)(Pl + lr0 * AP_LD + colL) = t;
            t.x=hb2; t.y=hb3; *(__nv_bfloat162*)(Ph + lr1 * AP_LD + colL) = t;
            t.x=lb2; t.y=lb3; *(__nv_bfloat162*)(Pl + lr1 * AP_LD + colL) = t;
        }
        sum0 += __shfl_xor_sync(0xffffffffu, sum0, 1);
        sum0 += __shfl_xor_sync(0xffffffffu, sum0, 2);
        sum1 += __shfl_xor_sync(0xffffffffu, sum1, 1);
        sum1 += __shfl_xor_sync(0xffffffffu, sum1, 2);
        if (tg == 0) { Sx[half * 64 + lr0] = sum0; Sx[half * 64 + lr1] = sum1; }
        asm volatile("bar.sync %0, 64;" :: "r"(barid) : "memory");   // E (pair)

        // one thread per row (warps 0-3, lanes 0-15) updates running state
        if (wid < 4 && lane < 16) {
            const int row = wm + lane;
            const float mo = Ms[row];
            const float mn = fmaxf(fmaxf(Mx[row], Mx[64 + row]), mo);
            const float corr = (mo == -INFINITY) ? 0.f : __expf(mo - mn);
            Ls[row] = Ls[row] * corr + Sx[row] + Sx[64 + row];
            Ms[row] = mn;
            Cr[row] = corr;
        }
        cpwait<0>();
        __syncthreads();   // F: V landed, Ph/Pl + Ls/Ms/Cr visible

        // Rescale accumulator, then O += P @ V (3-MMA split, ldmatrix)
        const float cr0 = Cr[wm + g], cr1 = Cr[wm + g + 8];
        #pragma unroll
        for (int nt = 0; nt < 16; nt++) {
            oc[nt][0] *= cr0; oc[nt][1] *= cr0;
            oc[nt][2] *= cr1; oc[nt][3] *= cr1;
        }
        #pragma unroll
        for (int kk = 0; kk < 64; kk += 16) {
            uint32_t pa[4], pl_[4];
            {
                const int ao = (wm + (m8 & 1) * 8 + ri) * AP_LD + kk + (m8 >> 1) * 8;
                ldsm_x4(pa,  Ph + ao);
                ldsm_x4(pl_, Pl + ao);
            }
            #pragma unroll
            for (int p = 0; p < 8; p++) {
                uint32_t bh[4], bl[4];
                const int bo = (wd + p * 16 + (m8 >> 1) * 8 + ri) * AP_LD + kk + (m8 & 1) * 8;
                ldsm_x4(bh, KVh + bo);
                ldsm_x4(bl, KVl + bo);
                #pragma unroll
                for (int sub = 0; sub < 2; sub++) {
                    const int nt = p * 2 + sub;
                    mma16816(oc[nt], pa,  bh[sub*2], bh[sub*2+1]);
                    mma16816(oc[nt], pa,  bl[sub*2], bl[sub*2+1]);
                    mma16816(oc[nt], pl_, bh[sub*2], bh[sub*2+1]);
                }
            }
        }
    }

    const float inv0 = 1.f / Ls[wm + g];
    const float inv1 = 1.f / Ls[wm + g + 8];
    #pragma unroll
    for (int nt = 0; nt < 16; nt++) {
        const int d = wd + nt * 8 + tg * 2;
        const size_t base0 = (size_t)(b * S_ + q0 + wm + g) * QKDIM_ + h * HD_ + d;
        const size_t base1 = base0 + 8 * QKDIM_;
        const float v0 = oc[nt][0] * inv0, v1 = oc[nt][1] * inv0;
        const float v2 = oc[nt][2] * inv1, v3 = oc[nt][3] * inv1;
        bf16 h0,l0,h1,l1,h2,l2,h3,l3;
        split1(v0,h0,l0); split1(v1,h1,l1); split1(v2,h2,l2); split1(v3,h3,l3);
        __nv_bfloat162 t;
        t.x=h0; t.y=h1; *(__nv_bfloat162*)(ath + base0) = t;
        t.x=l0; t.y=l1; *(__nv_bfloat162*)(atl + base0) = t;
        t.x=h2; t.y=h3; *(__nv_bfloat162*)(ath + base1) = t;
        t.x=l2; t.y=l3; *(__nv_bfloat162*)(atl + base1) = t;
    }
}

// ---------------------------------------------------------------------------
// Launch
// Inputs: 0=hidden_states 1=attention_mask(unused) 2=position_ids
//         3=Wq 4=Wk 5=Wv 6=Wo
// ---------------------------------------------------------------------------
extern "C" void kernel_launch(void* const* d_in, const int* in_sizes, int n_in,
                              void* d_out, int out_size) {
    (void)in_sizes; (void)n_in; (void)out_size;
    const float* hs  = (const float*)d_in[0];
    const int*   pos = (const int*)  d_in[2];
    const float* Wq  = (const float*)d_in[3];
    const float* Wk  = (const float*)d_in[4];
    const float* Wv  = (const float*)d_in[5];
    const float* Wo  = (const float*)d_in[6];
    float* out = (float*)d_out;

    float *qkv;
    bf16 *hsh,*hsl,*qh,*ql,*kh,*kl,*vth,*vtl,*ath,*atl;
    bf16 *wallh,*walll,*woh,*wol;
    cudaGetSymbolAddress((void**)&qkv, g_qkv);
    cudaGetSymbolAddress((void**)&hsh, g_hsh); cudaGetSymbolAddress((void**)&hsl, g_hsl);
    cudaGetSymbolAddress((void**)&qh,  g_qh);  cudaGetSymbolAddress((void**)&ql,  g_ql);
    cudaGetSymbolAddress((void**)&kh,  g_kh);  cudaGetSymbolAddress((void**)&kl,  g_kl);
    cudaGetSymbolAddress((void**)&vth, g_vth); cudaGetSymbolAddress((void**)&vtl, g_vtl);
    cudaGetSymbolAddress((void**)&ath, g_ath); cudaGetSymbolAddress((void**)&atl, g_atl);
    cudaGetSymbolAddress((void**)&wallh, g_wallh); cudaGetSymbolAddress((void**)&walll, g_walll);
    cudaGetSymbolAddress((void**)&woh, g_woh); cudaGetSymbolAddress((void**)&wol, g_wol);

    cudaFuncSetAttribute(gemm_bf16s,
        cudaFuncAttributeMaxDynamicSharedMemorySize, GEMM_SMEM);
    cudaFuncSetAttribute(attn_mma_kernel,
        cudaFuncAttributeMaxDynamicSharedMemorySize, ATT_SMEM_BYTES);

    const dim3 tb(32, 8);

    // Split hidden states; transpose+split weights into fused [2560][2048] B
    split_strided_kernel<<<(M_ * HID_ / 4 + 255) / 256, 256>>>(
        hs, hsh, hsl, M_ * HID_, 11, HID_);
    transpose_split_kernel<<<dim3(64, 64, 1), tb>>>(
        Wq, wallh, walll, QKDIM_, 0, HID_, 0);
    transpose_split_kernel<<<dim3(8, 64, 1), tb>>>(
        Wk, wallh + (size_t)QKDIM_ * HID_, walll + (size_t)QKDIM_ * HID_,
        HD_, 0, HID_, 0);
    transpose_split_kernel<<<dim3(8, 64, 1), tb>>>(
        Wv, wallh + (size_t)(QKDIM_ + HD_) * HID_, walll + (size_t)(QKDIM_ + HD_) * HID_,
        HD_, 0, HID_, 0);
    transpose_split_kernel<<<dim3(64, 64, 1), tb>>>(
        Wo, woh, wol, HID_, 0, QKDIM_, 0);

    // Fused QKV projection (tensor core): C[4096][2560]
    gemm_bf16s<<<dim3(NQKV_ / 128, M_ / 128), 256, GEMM_SMEM>>>(
        hsh, hsl, wallh, walll, qkv, M_, NQKV_, HID_);

    // Fused RoPE + split: qkv -> split Q/K directly
    {
        const int total = B_ * S_ * NH_ * (HD_ / 2) + B_ * S_ * (HD_ / 2);
        rope_split_kernel<<<(total + 255) / 256, 256>>>(qkv, pos, qh, ql, kh, kl);
    }

    // Transpose+split V per batch
    transpose_split_kernel<<<dim3(8, 64, B_), tb>>>(
        qkv + QKDIM_ + HD_, vth, vtl,
        NQKV_, (size_t)S_ * NQKV_, S_, (size_t)HD_ * S_);

    // Attention (tensor core flash)
    attn_mma_kernel<<<dim3(S_ / 64, NH_, B_), 256, ATT_SMEM_BYTES>>>(
        qh, ql, kh, kl, vth, vtl, ath, atl);

    // Output projection (tensor core)
    gemm_bf16s<<<dim3(HID_ / 128, M_ / 128), 256, GEMM_SMEM>>>(
        ath, atl, woh, wol, out, M_, HID_, HID_);
}

// round 10
// speedup vs baseline: 2.9703x; 1.1018x over previous
#include <cuda_runtime.h>
#include <cuda_bf16.h>
#include <math.h>
#include <stdint.h>

// Problem constants
#define B_ 2
#define S_ 2048
#define HID_ 2048
#define NH_ 8
#define HD_ 256
#define M_ 4096           // B*S
#define QKDIM_ (NH_*HD_)  // 2048
#define NQKV_ 2560        // 2048 (Q) + 256 (K) + 256 (V)

typedef __nv_bfloat16 bf16;

// ---------------------------------------------------------------------------
// Scratch (device globals: allocation-free per harness rules)
// ---------------------------------------------------------------------------
__device__ float g_qkv[M_ * NQKV_];                         // fused QKV output (fp32)

__device__ bf16 g_hsh[M_ * HID_],  g_hsl[M_ * HID_];        // split hidden_states
__device__ bf16 g_qh [M_ * QKDIM_], g_ql [M_ * QKDIM_];     // split Q (post-RoPE)
__device__ bf16 g_kh [M_ * HD_],   g_kl [M_ * HD_];         // split K
__device__ bf16 g_vth[B_ * HD_ * S_], g_vtl[B_ * HD_ * S_]; // V transposed [b][d][s]
__device__ bf16 g_ath[M_ * QKDIM_], g_atl[M_ * QKDIM_];     // split attention output

__device__ bf16 g_wallh[NQKV_ * HID_];                      // fused [Wq;Wk;Wv]^T hi
__device__ bf16 g_walll[NQKV_ * HID_];                      // fused lo
__device__ bf16 g_woh[QKDIM_ * HID_], g_wol[QKDIM_ * HID_];

// ---------------------------------------------------------------------------
// Helpers
// ---------------------------------------------------------------------------
__device__ __forceinline__ void split1(float x, bf16& h, bf16& l) {
    h = __float2bfloat16(x);
    l = __float2bfloat16(x - __bfloat162float(h));
}

__device__ __forceinline__ void mma16816(float (&d)[4], const uint32_t (&a)[4],
                                         uint32_t b0, uint32_t b1) {
    asm volatile(
        "mma.sync.aligned.m16n8k16.row.col.f32.bf16.bf16.f32 "
        "{%0,%1,%2,%3}, {%4,%5,%6,%7}, {%8,%9}, {%0,%1,%2,%3};\n"
        : "+f"(d[0]), "+f"(d[1]), "+f"(d[2]), "+f"(d[3])
        : "r"(a[0]), "r"(a[1]), "r"(a[2]), "r"(a[3]), "r"(b0), "r"(b1));
}

__device__ __forceinline__ void ldsm_x4(uint32_t (&r)[4], const bf16* p) {
    uint32_t a = (uint32_t)__cvta_generic_to_shared(p);
    asm volatile("ldmatrix.sync.aligned.m8n8.x4.shared.b16 {%0,%1,%2,%3}, [%4];\n"
        : "=r"(r[0]), "=r"(r[1]), "=r"(r[2]), "=r"(r[3]) : "r"(a));
}

__device__ __forceinline__ void cpasync16(bf16* s, const bf16* g) {
    uint32_t sa = (uint32_t)__cvta_generic_to_shared(s);
    asm volatile("cp.async.cg.shared.global [%0], [%1], 16;\n" :: "r"(sa), "l"(g));
}
__device__ __forceinline__ void cpcommit() {
    asm volatile("cp.async.commit_group;\n");
}
template<int N> __device__ __forceinline__ void cpwait() {
    asm volatile("cp.async.wait_group %0;\n" :: "n"(N));
}

// ---------------------------------------------------------------------------
// Elementwise split with strided source.
// ---------------------------------------------------------------------------
__global__ void split_strided_kernel(const float* __restrict__ in,
                                     bf16* __restrict__ oh, bf16* __restrict__ ol,
                                     int n, int colshift, int ldin) {
    int i = (blockIdx.x * blockDim.x + threadIdx.x) * 4;
    if (i >= n) return;
    int r = i >> colshift;
    int c = i & ((1 << colshift) - 1);
    float4 v = *(const float4*)(in + (size_t)r * ldin + c);
    bf16 h0,l0,h1,l1,h2,l2,h3,l3;
    split1(v.x,h0,l0); split1(v.y,h1,l1); split1(v.z,h2,l2); split1(v.w,h3,l3);
    __nv_bfloat162 a, b;
    a.x=h0; a.y=h1; b.x=h2; b.y=h3;
    *(__nv_bfloat162*)(oh+i)   = a; *(__nv_bfloat162*)(oh+i+2) = b;
    a.x=l0; a.y=l1; b.x=l2; b.y=l3;
    *(__nv_bfloat162*)(ol+i)   = a; *(__nv_bfloat162*)(ol+i+2) = b;
}

// ---------------------------------------------------------------------------
// Tiled transpose + split.
// ---------------------------------------------------------------------------
__global__ void transpose_split_kernel(const float* __restrict__ in,
                                       bf16* __restrict__ oh, bf16* __restrict__ ol,
                                       int ldin, size_t bsIn, int ldout, size_t bsOut) {
    __shared__ float t[32][33];
    const float* ip = in + (size_t)blockIdx.z * bsIn;
    bf16* ohp = oh + (size_t)blockIdx.z * bsOut;
    bf16* olp = ol + (size_t)blockIdx.z * bsOut;
    const int r0 = blockIdx.y * 32, c0 = blockIdx.x * 32;
    #pragma unroll
    for (int i = 0; i < 4; i++) {
        int r = threadIdx.y + i * 8;
        t[r][threadIdx.x] = ip[(size_t)(r0 + r) * ldin + c0 + threadIdx.x];
    }
    __syncthreads();
    #pragma unroll
    for (int i = 0; i < 4; i++) {
        int c = threadIdx.y + i * 8;
        float v = t[threadIdx.x][c];
        bf16 h, l; split1(v, h, l);
        size_t o = (size_t)(c0 + c) * ldout + r0 + threadIdx.x;
        ohp[o] = h; olp[o] = l;
    }
}

// ---------------------------------------------------------------------------
// GEMM: C[M,N] = A[M,K] @ B^T, A split bf16 [M][K], B split bf16 [N][K].
// 128x128 tile, BK=32, 256 threads (8 warps 4x2, warp tile 32x64).
// 2-stage cp.async pipeline + ldmatrix + 3-MMA bf16 split.
// __launch_bounds__(256,2): cap regs at 128 so 2 CTAs/SM colocate
// (80KB smem/CTA) -> 4 warps/SMSP to hide latency.
// ---------------------------------------------------------------------------
#define GLDA 40                    // 32 + 8 halves pad (80B row: LDSM conflict-free)
#define PLANEH (128 * GLDA)        // 5120 halves per plane
#define STAGEH (4 * PLANEH)        // Ah, Al, Bh, Bl
#define GEMM_SMEM (2 * STAGEH * 2) // 2 stages: 81920 bytes

__global__ __launch_bounds__(256, 2) void gemm_bf16s(
    const bf16* __restrict__ Ah, const bf16* __restrict__ Al,
    const bf16* __restrict__ Bh, const bf16* __restrict__ Bl,
    float* __restrict__ C, int M, int N, int K)
{
    extern __shared__ bf16 sm[];
    const int tid = threadIdx.x;
    const int wid = tid >> 5, lane = tid & 31;
    const int g = lane >> 2, tg = lane & 3;
    const int m8 = lane >> 3, ri = lane & 7;     // ldmatrix lane decomposition
    const int wm = (wid & 3) * 32;
    const int wn = (wid >> 2) * 64;
    const int row0 = blockIdx.y * 128;
    const int col0 = blockIdx.x * 128;

    // cp.async mapping: thread -> row tid>>1, halves col (tid&1)*16
    const int lr = tid >> 1;
    const int lc = (tid & 1) * 16;
    const bf16* gA  = Ah + (size_t)(row0 + lr) * K + lc;
    const bf16* gAl = Al + (size_t)(row0 + lr) * K + lc;
    const bf16* gB  = Bh + (size_t)(col0 + lr) * K + lc;
    const bf16* gBl = Bl + (size_t)(col0 + lr) * K + lc;
    const int soff = lr * GLDA + lc;

    float acc[2][8][4] = {};
    const int nk = K / 32;

    auto load_stage = [&](int chunk, int st) {
        const int k0 = chunk * 32;
        bf16* s = sm + st * STAGEH + soff;
        cpasync16(s,            gA  + k0);  cpasync16(s + 8,            gA  + k0 + 8);
        cpasync16(s + PLANEH,   gAl + k0);  cpasync16(s + PLANEH + 8,   gAl + k0 + 8);
        cpasync16(s + 2*PLANEH, gB  + k0);  cpasync16(s + 2*PLANEH + 8, gB  + k0 + 8);
        cpasync16(s + 3*PLANEH, gBl + k0);  cpasync16(s + 3*PLANEH + 8, gBl + k0 + 8);
        cpcommit();
    };

    load_stage(0, 0);

    for (int i = 0; i < nk; i++) {
        if (i + 1 < nk) {
            load_stage(i + 1, (i + 1) & 1);
            cpwait<1>();
        } else {
            cpwait<0>();
        }
        __syncthreads();

        const bf16* pAh = sm + (i & 1) * STAGEH;
        const bf16* pAl = pAh + PLANEH;
        const bf16* pBh = pAh + 2 * PLANEH;
        const bf16* pBl = pAh + 3 * PLANEH;

        #pragma unroll
        for (int kk = 0; kk < 32; kk += 16) {
            uint32_t ah[2][4], al[2][4];
            #pragma unroll
            for (int mt = 0; mt < 2; mt++) {
                const int ao = (wm + mt * 16 + (m8 & 1) * 8 + ri) * GLDA + kk + (m8 >> 1) * 8;
                ldsm_x4(ah[mt], pAh + ao);
                ldsm_x4(al[mt], pAl + ao);
            }
            uint32_t bh[4][4], bl[4][4];
            #pragma unroll
            for (int p = 0; p < 4; p++) {
                const int bo = (wn + p * 16 + (m8 >> 1) * 8 + ri) * GLDA + kk + (m8 & 1) * 8;
                ldsm_x4(bh[p], pBh + bo);
                ldsm_x4(bl[p], pBl + bo);
            }
            #pragma unroll
            for (int p = 0; p < 4; p++)
                #pragma unroll
                for (int sub = 0; sub < 2; sub++) {
                    const int nt = p * 2 + sub;
                    const uint32_t h0 = bh[p][sub*2], h1 = bh[p][sub*2+1];
                    const uint32_t l0 = bl[p][sub*2], l1 = bl[p][sub*2+1];
                    #pragma unroll
                    for (int mt = 0; mt < 2; mt++) {
                        mma16816(acc[mt][nt], ah[mt], h0, h1);
                        mma16816(acc[mt][nt], ah[mt], l0, l1);
                        mma16816(acc[mt][nt], al[mt], h0, h1);
                    }
                }
        }
        __syncthreads();
    }

    #pragma unroll
    for (int mt = 0; mt < 2; mt++)
        #pragma unroll
        for (int nt = 0; nt < 8; nt++) {
            const int r  = row0 + wm + mt * 16 + g;
            const int cn = col0 + wn + nt * 8 + tg * 2;
            float2 v01; v01.x = acc[mt][nt][0]; v01.y = acc[mt][nt][1];
            float2 v23; v23.x = acc[mt][nt][2]; v23.y = acc[mt][nt][3];
            *(float2*)(C + (size_t)r * N + cn)       = v01;
            *(float2*)(C + (size_t)(r + 8) * N + cn) = v23;
        }
}

// ---------------------------------------------------------------------------
// Fused RoPE + split: reads fp32 pairs from qkv, rotates, writes split bf16
// directly into qh/ql (Q) and kh/kl (K). qkv itself is left untouched.
// ---------------------------------------------------------------------------
__global__ void rope_split_kernel(const float* __restrict__ qkv,
                                  const int* __restrict__ pos,
                                  bf16* __restrict__ qh, bf16* __restrict__ ql,
                                  bf16* __restrict__ kh, bf16* __restrict__ kl)
{
    const int QP = B_ * S_ * NH_ * (HD_ / 2);
    const int KP = B_ * S_ * (HD_ / 2);
    int idx = blockIdx.x * blockDim.x + threadIdx.x;
    if (idx >= QP + KP) return;
    const float L2B = 13.28771237954945f;  // log2(10000)

    int i, bs;
    const float* base;
    bf16 *oh, *ol;
    size_t oo;
    if (idx < QP) {
        i  = idx & 127;
        const int h = (idx >> 7) & 7;
        bs = idx >> 10;
        base = qkv + (size_t)bs * NQKV_ + h * HD_;
        oo = (size_t)bs * QKDIM_ + h * HD_;
        oh = qh; ol = ql;
    } else {
        const int j = idx - QP;
        i  = j & 127;
        bs = j >> 7;
        base = qkv + (size_t)bs * NQKV_ + QKDIM_;
        oo = (size_t)bs * HD_;
        oh = kh; ol = kl;
    }
    const float inv = exp2f(-(float)(2 * i) * (L2B / 256.f));
    const float ang = (float)pos[bs] * inv;
    float sn, cs; sincosf(ang, &sn, &cs);
    const float x1 = base[i], x2 = base[i + 128];
    const float o1 = x1 * cs - x2 * sn;
    const float o2 = x2 * cs + x1 * sn;
    bf16 h1, l1, h2, l2;
    split1(o1, h1, l1); split1(o2, h2, l2);
    oh[oo + i]       = h1;  ol[oo + i]       = l1;
    oh[oo + i + 128] = h2;  ol[oo + i + 128] = l2;
}

// ---------------------------------------------------------------------------
// Flash attention, bf16-split MMAs + ldmatrix.
// Pipelined loads: separate K and V SMEM buffers — V(kt) issued before S-MMA
// (hidden under it), K(kt+1) issued after S-MMA reads K (hidden under
// softmax + PV). In-register softmax (shfl + pair-warp exchange).
// ---------------------------------------------------------------------------
#define AQ_LD 264
#define AP_LD 72
#define AQ_HALVES (64 * AQ_LD)    // 16896 (per plane, Q and K tiles)
#define AV_HALVES (256 * AP_LD)   // 18432 (per plane, V tile)
#define APB_HALVES (64 * AP_LD)   // 4608  (per plane, P tile)

#define ATT_SMEM_BYTES ((4*AQ_HALVES + 2*AV_HALVES + 2*APB_HALVES) * 2 + (3*64 + 256) * 4)

__global__ __launch_bounds__(256, 1) void attn_mma_kernel(
    const bf16* __restrict__ qh, const bf16* __restrict__ ql,
    const bf16* __restrict__ kh, const bf16* __restrict__ kl,
    const bf16* __restrict__ vth, const bf16* __restrict__ vtl,
    bf16* __restrict__ ath, bf16* __restrict__ atl)
{
    extern __shared__ char smraw[];
    bf16* Qh = (bf16*)smraw;
    bf16* Ql = Qh + AQ_HALVES;
    bf16* Kh = Ql + AQ_HALVES;
    bf16* Kl = Kh + AQ_HALVES;
    bf16* Vh = Kl + AQ_HALVES;
    bf16* Vl = Vh + AV_HALVES;
    bf16* Ph = Vl + AV_HALVES;
    bf16* Pl = Ph + APB_HALVES;
    float* Ms = (float*)(Pl + APB_HALVES);
    float* Ls = Ms + 64;
    float* Cr = Ls + 64;
    float* Mx = Cr + 64;    // [128] pair-warp max exchange
    float* Sx = Mx + 128;   // [128] pair-warp sum exchange

    const int qt = (int)gridDim.x - 1 - (int)blockIdx.x;  // heavy tiles first
    const int h  = blockIdx.y;
    const int b  = blockIdx.z;
    const int tid = threadIdx.x;
    const int wid = tid >> 5, lane = tid & 31;
    const int g = lane >> 2, tg = lane & 3;
    const int m8 = lane >> 3, ri = lane & 7;
    const int wm  = (wid & 3) * 16;
    const int wn2 = (wid >> 2) * 32;
    const int wd  = (wid >> 2) * 128;
    const int half = wid >> 2;
    const int barid = (wid & 3) + 1;
    const int q0 = qt * 64;
    const float scale = 0.0625f;

    // prologue: Q tile (group) then K(0) tile (group)
    {
        #pragma unroll
        for (int j = 0; j < 8; j++) {
            const int c = tid + 256 * j;
            const int r = c >> 5, cc = (c & 31) * 8;
            const size_t go = (size_t)(b * S_ + q0 + r) * QKDIM_ + h * HD_ + cc;
            cpasync16(Qh + r * AQ_LD + cc, qh + go);
            cpasync16(Ql + r * AQ_LD + cc, ql + go);
        }
        cpcommit();
        #pragma unroll
        for (int j = 0; j < 8; j++) {
            const int c = tid + 256 * j;
            const int r = c >> 5, cc = (c & 31) * 8;
            const size_t go = (size_t)(b * S_ + r) * HD_ + cc;
            cpasync16(Kh + r * AQ_LD + cc, kh + go);
            cpasync16(Kl + r * AQ_LD + cc, kl + go);
        }
        cpcommit();
    }
    if (tid < 64) { Ms[tid] = -INFINITY; Ls[tid] = 0.f; Cr[tid] = 0.f; }

    float oc[16][4] = {};

    for (int kt = 0; kt <= qt; ++kt) {
        const int k0 = kt * 64;
        cpwait<0>();       // K(kt) (and Q on first iter) landed
        __syncthreads();   // B: K visible; PV(kt-1) done with V and P buffers

        // Issue V(kt) load now — hidden under S-MMA.
        #pragma unroll
        for (int j = 0; j < 8; j++) {
            const int c = tid + 256 * j;
            const int r = c >> 3, cc = (c & 7) * 8;
            const size_t go = (size_t)b * HD_ * S_ + (size_t)r * S_ + k0 + cc;
            cpasync16(Vh + r * AP_LD + cc, vth + go);
            cpasync16(Vl + r * AP_LD + cc, vtl + go);
        }
        cpcommit();        // group V

        // S = Q @ K^T via 3-MMA split (ldmatrix fragments)
        float sc[4][4] = {};
        #pragma unroll
        for (int kk = 0; kk < 256; kk += 16) {
            uint32_t ah[4], al[4];
            {
                const int ao = (wm + (m8 & 1) * 8 + ri) * AQ_LD + kk + (m8 >> 1) * 8;
                ldsm_x4(ah, Qh + ao);
                ldsm_x4(al, Ql + ao);
            }
            uint32_t bh[2][4], bl[2][4];
            #pragma unroll
            for (int p = 0; p < 2; p++) {
                const int bo = (wn2 + p * 16 + (m8 >> 1) * 8 + ri) * AQ_LD + kk + (m8 & 1) * 8;
                ldsm_x4(bh[p], Kh + bo);
                ldsm_x4(bl[p], Kl + bo);
            }
            #pragma unroll
            for (int p = 0; p < 2; p++)
                #pragma unroll
                for (int sub = 0; sub < 2; sub++) {
                    const int nt = p * 2 + sub;
                    mma16816(sc[nt], ah, bh[p][sub*2], bh[p][sub*2+1]);
                    mma16816(sc[nt], ah, bl[p][sub*2], bl[p][sub*2+1]);
                    mma16816(sc[nt], al, bh[p][sub*2], bh[p][sub*2+1]);
                }
        }

        // scale + causal mask in registers
        const int r0g = q0 + wm + g;
        const int r1g = r0g + 8;
        #pragma unroll
        for (int nt = 0; nt < 4; nt++) {
            const int col = k0 + wn2 + nt * 8 + tg * 2;
            sc[nt][0] = (col     > r0g) ? -1e30f : sc[nt][0] * scale;
            sc[nt][1] = (col + 1 > r0g) ? -1e30f : sc[nt][1] * scale;
            sc[nt][2] = (col     > r1g) ? -1e30f : sc[nt][2] * scale;
            sc[nt][3] = (col + 1 > r1g) ? -1e30f : sc[nt][3] * scale;
        }

        __syncthreads();   // C: all warps done reading K(kt)

        // Issue K(kt+1) load — hidden under softmax + PV.
        if (kt < qt) {
            const int kn = k0 + 64;
            #pragma unroll
            for (int j = 0; j < 8; j++) {
                const int c = tid + 256 * j;
                const int r = c >> 5, cc = (c & 31) * 8;
                const size_t go = (size_t)(b * S_ + kn + r) * HD_ + cc;
                cpasync16(Kh + r * AQ_LD + cc, kh + go);
                cpasync16(Kl + r * AQ_LD + cc, kl + go);
            }
            cpcommit();    // group K(kt+1)
        }

        // In-register softmax. Rows r0=wm+g, r1=r0+8; 8 cols/row per thread.
        const int lr0 = wm + g, lr1 = lr0 + 8;
        float mx0 = -INFINITY, mx1 = -INFINITY;
        #pragma unroll
        for (int nt = 0; nt < 4; nt++) {
            mx0 = fmaxf(mx0, fmaxf(sc[nt][0], sc[nt][1]));
            mx1 = fmaxf(mx1, fmaxf(sc[nt][2], sc[nt][3]));
        }
        mx0 = fmaxf(mx0, __shfl_xor_sync(0xffffffffu, mx0, 1));
        mx0 = fmaxf(mx0, __shfl_xor_sync(0xffffffffu, mx0, 2));
        mx1 = fmaxf(mx1, __shfl_xor_sync(0xffffffffu, mx1, 1));
        mx1 = fmaxf(mx1, __shfl_xor_sync(0xffffffffu, mx1, 2));
        if (tg == 0) { Mx[half * 64 + lr0] = mx0; Mx[half * 64 + lr1] = mx1; }
        asm volatile("bar.sync %0, 64;" :: "r"(barid) : "memory");   // D (pair)

        const float mo0 = Ms[lr0], mo1 = Ms[lr1];
        const float mn0 = fmaxf(fmaxf(Mx[lr0], Mx[64 + lr0]), mo0);
        const float mn1 = fmaxf(fmaxf(Mx[lr1], Mx[64 + lr1]), mo1);
        float sum0 = 0.f, sum1 = 0.f;
        #pragma unroll
        for (int nt = 0; nt < 4; nt++) {
            const int colL = wn2 + nt * 8 + tg * 2;
            const float p0 = __expf(sc[nt][0] - mn0);
            const float p1 = __expf(sc[nt][1] - mn0);
            const float p2 = __expf(sc[nt][2] - mn1);
            const float p3 = __expf(sc[nt][3] - mn1);
            sum0 += p0 + p1; sum1 += p2 + p3;
            bf16 hb0,lb0,hb1,lb1,hb2,lb2,hb3,lb3;
            split1(p0,hb0,lb0); split1(p1,hb1,lb1);
            split1(p2,hb2,lb2); split1(p3,hb3,lb3);
            __nv_bfloat162 t;
            t.x=hb0; t.y=hb1; *(__nv_bfloat162*)(Ph + lr0 * AP_LD + colL) = t;
            t.x=lb0; t.y=lb1; *(__nv_bfloat162*)(Pl + lr0 * AP_LD + colL) = t;
            t.x=hb2; t.y=hb3; *(__nv_bfloat162*)(Ph + lr1 * AP_LD + colL) = t;
            t.x=lb2; t.y=lb3; *(__nv_bfloat162*)(Pl + lr1 * AP_LD + colL) = t;
        }
        sum0 += __shfl_xor_sync(0xffffffffu, sum0, 1);
        sum0 += __shfl_xor_sync(0xffffffffu, sum0, 2);
        sum1 += __shfl_xor_sync(0xffffffffu, sum1, 1);
        sum1 += __shfl_xor_sync(0xffffffffu, sum1, 2);
        if (tg == 0) { Sx[half * 64 + lr0] = sum0; Sx[half * 64 + lr1] = sum1; }
        asm volatile("bar.sync %0, 64;" :: "r"(barid) : "memory");   // E (pair)

        // one thread per row (warps 0-3, lanes 0-15) updates running state
        if (wid < 4 && lane < 16) {
            const int row = wm + lane;
            const float mo = Ms[row];
            const float mn = fmaxf(fmaxf(Mx[row], Mx[64 + row]), mo);
            const float corr = (mo == -INFINITY) ? 0.f : __expf(mo - mn);
            Ls[row] = Ls[row] * corr + Sx[row] + Sx[64 + row];
            Ms[row] = mn;
            Cr[row] = corr;
        }
        // V must be complete; K(kt+1) (the most recent group) may stay in flight.
        if (kt < qt) cpwait<1>(); else cpwait<0>();
        __syncthreads();   // F: V landed, Ph/Pl + Ls/Ms/Cr visible

        // Rescale accumulator, then O += P @ V (3-MMA split, ldmatrix)
        const float cr0 = Cr[wm + g], cr1 = Cr[wm + g + 8];
        #pragma unroll
        for (int nt = 0; nt < 16; nt++) {
            oc[nt][0] *= cr0; oc[nt][1] *= cr0;
            oc[nt][2] *= cr1; oc[nt][3] *= cr1;
        }
        #pragma unroll
        for (int kk = 0; kk < 64; kk += 16) {
            uint32_t pa[4], pl_[4];
            {
                const int ao = (wm + (m8 & 1) * 8 + ri) * AP_LD + kk + (m8 >> 1) * 8;
                ldsm_x4(pa,  Ph + ao);
                ldsm_x4(pl_, Pl + ao);
            }
            #pragma unroll
            for (int p = 0; p < 8; p++) {
                uint32_t bh[4], bl[4];
                const int bo = (wd + p * 16 + (m8 >> 1) * 8 + ri) * AP_LD + kk + (m8 & 1) * 8;
                ldsm_x4(bh, Vh + bo);
                ldsm_x4(bl, Vl + bo);
                #pragma unroll
                for (int sub = 0; sub < 2; sub++) {
                    const int nt = p * 2 + sub;
                    mma16816(oc[nt], pa,  bh[sub*2], bh[sub*2+1]);
                    mma16816(oc[nt], pa,  bl[sub*2], bl[sub*2+1]);
                    mma16816(oc[nt], pl_, bh[sub*2], bh[sub*2+1]);
                }
            }
        }
    }

    const float inv0 = 1.f / Ls[wm + g];
    const float inv1 = 1.f / Ls[wm + g + 8];
    #pragma unroll
    for (int nt = 0; nt < 16; nt++) {
        const int d = wd + nt * 8 + tg * 2;
        const size_t base0 = (size_t)(b * S_ + q0 + wm + g) * QKDIM_ + h * HD_ + d;
        const size_t base1 = base0 + 8 * QKDIM_;
        const float v0 = oc[nt][0] * inv0, v1 = oc[nt][1] * inv0;
        const float v2 = oc[nt][2] * inv1, v3 = oc[nt][3] * inv1;
        bf16 h0,l0,h1,l1,h2,l2,h3,l3;
        split1(v0,h0,l0); split1(v1,h1,l1); split1(v2,h2,l2); split1(v3,h3,l3);
        __nv_bfloat162 t;
        t.x=h0; t.y=h1; *(__nv_bfloat162*)(ath + base0) = t;
        t.x=l0; t.y=l1; *(__nv_bfloat162*)(atl + base0) = t;
        t.x=h2; t.y=h3; *(__nv_bfloat162*)(ath + base1) = t;
        t.x=l2; t.y=l3; *(__nv_bfloat162*)(atl + base1) = t;
    }
}

// ---------------------------------------------------------------------------
// Launch
// Inputs: 0=hidden_states 1=attention_mask(unused) 2=position_ids
//         3=Wq 4=Wk 5=Wv 6=Wo
// ---------------------------------------------------------------------------
extern "C" void kernel_launch(void* const* d_in, const int* in_sizes, int n_in,
                              void* d_out, int out_size) {
    (void)in_sizes; (void)n_in; (void)out_size;
    const float* hs  = (const float*)d_in[0];
    const int*   pos = (const int*)  d_in[2];
    const float* Wq  = (const float*)d_in[3];
    const float* Wk  = (const float*)d_in[4];
    const float* Wv  = (const float*)d_in[5];
    const float* Wo  = (const float*)d_in[6];
    float* out = (float*)d_out;

    float *qkv;
    bf16 *hsh,*hsl,*qh,*ql,*kh,*kl,*vth,*vtl,*ath,*atl;
    bf16 *wallh,*walll,*woh,*wol;
    cudaGetSymbolAddress((void**)&qkv, g_qkv);
    cudaGetSymbolAddress((void**)&hsh, g_hsh); cudaGetSymbolAddress((void**)&hsl, g_hsl);
    cudaGetSymbolAddress((void**)&qh,  g_qh);  cudaGetSymbolAddress((void**)&ql,  g_ql);
    cudaGetSymbolAddress((void**)&kh,  g_kh);  cudaGetSymbolAddress((void**)&kl,  g_kl);
    cudaGetSymbolAddress((void**)&vth, g_vth); cudaGetSymbolAddress((void**)&vtl, g_vtl);
    cudaGetSymbolAddress((void**)&ath, g_ath); cudaGetSymbolAddress((void**)&atl, g_atl);
    cudaGetSymbolAddress((void**)&wallh, g_wallh); cudaGetSymbolAddress((void**)&walll, g_walll);
    cudaGetSymbolAddress((void**)&woh, g_woh); cudaGetSymbolAddress((void**)&wol, g_wol);

    cudaFuncSetAttribute(gemm_bf16s,
        cudaFuncAttributeMaxDynamicSharedMemorySize, GEMM_SMEM);
    cudaFuncSetAttribute(attn_mma_kernel,
        cudaFuncAttributeMaxDynamicSharedMemorySize, ATT_SMEM_BYTES);

    const dim3 tb(32, 8);

    // Split hidden states; transpose+split weights into fused [2560][2048] B
    split_strided_kernel<<<(M_ * HID_ / 4 + 255) / 256, 256>>>(
        hs, hsh, hsl, M_ * HID_, 11, HID_);
    transpose_split_kernel<<<dim3(64, 64, 1), tb>>>(
        Wq, wallh, walll, QKDIM_, 0, HID_, 0);
    transpose_split_kernel<<<dim3(8, 64, 1), tb>>>(
        Wk, wallh + (size_t)QKDIM_ * HID_, walll + (size_t)QKDIM_ * HID_,
        HD_, 0, HID_, 0);
    transpose_split_kernel<<<dim3(8, 64, 1), tb>>>(
        Wv, wallh + (size_t)(QKDIM_ + HD_) * HID_, walll + (size_t)(QKDIM_ + HD_) * HID_,
        HD_, 0, HID_, 0);
    transpose_split_kernel<<<dim3(64, 64, 1), tb>>>(
        Wo, woh, wol, HID_, 0, QKDIM_, 0);

    // Fused QKV projection (tensor core): C[4096][2560]
    gemm_bf16s<<<dim3(NQKV_ / 128, M_ / 128), 256, GEMM_SMEM>>>(
        hsh, hsl, wallh, walll, qkv, M_, NQKV_, HID_);

    // Fused RoPE + split: qkv -> split Q/K directly
    {
        const int total = B_ * S_ * NH_ * (HD_ / 2) + B_ * S_ * (HD_ / 2);
        rope_split_kernel<<<(total + 255) / 256, 256>>>(qkv, pos, qh, ql, kh, kl);
    }

    // Transpose+split V per batch
    transpose_split_kernel<<<dim3(8, 64, B_), tb>>>(
        qkv + QKDIM_ + HD_, vth, vtl,
        NQKV_, (size_t)S_ * NQKV_, S_, (size_t)HD_ * S_);

    // Attention (tensor core flash)
    attn_mma_kernel<<<dim3(S_ / 64, NH_, B_), 256, ATT_SMEM_BYTES>>>(
        qh, ql, kh, kl, vth, vtl, ath, atl);

    // Output projection (tensor core)
    gemm_bf16s<<<dim3(HID_ / 128, M_ / 128), 256, GEMM_SMEM>>>(
        ath, atl, woh, wol, out, M_, HID_, HID_);
}